// round 6
// baseline (speedup 1.0000x reference)
#include <cuda_runtime.h>
#include <math.h>

// Problem constants
#define Bn 2
#define Sn 2048
#define En 1024
#define Hn 16
#define Dn 64
#define Mn (Bn*Sn)   // 4096 rows

// Scratch (static __device__ arrays: allocation-guard safe)
__device__ float g_Q[Bn*Hn*Sn*Dn];   // [B,H,S,D]
__device__ float g_K[Bn*Hn*Sn*Dn];
__device__ float g_V[Bn*Hn*Sn*Dn];
__device__ float g_A[Mn*En];         // attention output, [B,S,E]
__device__ float g_maskf[Bn*Sn];     // normalized mask: 1.0 = masked out

// ---------------------------------------------------------------------------
// Mask prep: sniff dtype (uint8 / int32 / float32) from the FIRST 4096 bytes
// (safe under every hypothesis), then normalize to float flags.
//   uint8  : random 0/1 bytes everywhere -> nonzero at offset%4==1
//   int32  : 0/1 little-endian           -> nonzero only at offset%4==0
//   float32: 1.0f = 00 00 80 3F          -> nonzero only at offset%4 in {2,3}
// ---------------------------------------------------------------------------
__global__ void mask_prep(const unsigned char* __restrict__ m)
{
    __shared__ int s_cnt[2];          // [0]: offset%4==1 nonzero, [1]: %4==0
    const int tid = threadIdx.x;
    if (tid < 2) s_cnt[tid] = 0;
    __syncthreads();

    int c1 = 0, c0 = 0;
    for (int i = tid; i < (Bn*Sn)/4; i += blockDim.x) {
        uchar4 v = ((const uchar4*)m)[i];     // bytes 4i..4i+3 (< 4096)
        if (v.y) c1++;
        if (v.x) c0++;
    }
    atomicAdd(&s_cnt[0], c1);
    atomicAdd(&s_cnt[1], c0);
    __syncthreads();

    const int mode = (s_cnt[0] > 0) ? 0 : ((s_cnt[1] > 0) ? 1 : 2);
    for (int i = tid; i < Bn*Sn; i += blockDim.x) {
        float f;
        if (mode == 0)      f = m[i] ? 1.f : 0.f;
        else if (mode == 1) f = (((const int*)m)[i] != 0) ? 1.f : 0.f;
        else                f = (((const float*)m)[i] != 0.f) ? 1.f : 0.f;
        g_maskf[i] = f;
    }
}

// ---------------------------------------------------------------------------
// SGEMM: C[M,N] = A[M,K] * W[N,K]^T + bias  (torch Linear convention)
// 128x128 tile, BK=8, 256 threads, 8x8 per thread.
// MODE 1: QKV — blockIdx.z selects (W,b), writes head-transposed to g_Q/K/V.
// MODE 0: out-projection — reads g_A, writes outp[m*E + n].
// ---------------------------------------------------------------------------
template<int MODE>
__global__ __launch_bounds__(256)
void gemm_kernel(const float* __restrict__ A,
                 const float* __restrict__ W0, const float* __restrict__ bias0,
                 const float* __restrict__ W1, const float* __restrict__ bias1,
                 const float* __restrict__ W2, const float* __restrict__ bias2,
                 float* __restrict__ outp)
{
    const float* W    = W0;
    const float* bias = bias0;
    float* outq = nullptr;
    if (MODE == 1) {
        int z = blockIdx.z;
        W    = (z==0) ? W0    : ((z==1) ? W1    : W2);
        bias = (z==0) ? bias0 : ((z==1) ? bias1 : bias2);
        outq = (z==0) ? g_Q   : ((z==1) ? g_K   : g_V);
    }
    const float* Ap = (MODE == 1) ? A : g_A;

    __shared__ float As[8][128];
    __shared__ float Ws[8][128];

    const int tid = threadIdx.x;
    const int tx = tid & 15;
    const int ty = tid >> 4;
    const int m0 = blockIdx.y * 128;
    const int n0 = blockIdx.x * 128;
    const int lrow = tid >> 1;         // 0..127
    const int lc4  = (tid & 1) * 4;    // 0 or 4

    float c[8][8];
    #pragma unroll
    for (int i = 0; i < 8; i++)
        #pragma unroll
        for (int j = 0; j < 8; j++) c[i][j] = 0.f;

    for (int k0 = 0; k0 < En; k0 += 8) {
        float4 av = *(const float4*)&Ap[(m0 + lrow)*En + k0 + lc4];
        float4 wv = *(const float4*)&W [(n0 + lrow)*En + k0 + lc4];
        As[lc4+0][lrow] = av.x; As[lc4+1][lrow] = av.y;
        As[lc4+2][lrow] = av.z; As[lc4+3][lrow] = av.w;
        Ws[lc4+0][lrow] = wv.x; Ws[lc4+1][lrow] = wv.y;
        Ws[lc4+2][lrow] = wv.z; Ws[lc4+3][lrow] = wv.w;
        __syncthreads();
        #pragma unroll
        for (int k = 0; k < 8; k++) {
            float4 a0 = *(const float4*)&As[k][(ty<<2)];
            float4 a1 = *(const float4*)&As[k][(ty<<2) + 64];
            float4 b0 = *(const float4*)&Ws[k][(tx<<2)];
            float4 b1 = *(const float4*)&Ws[k][(tx<<2) + 64];
            float ra[8] = {a0.x,a0.y,a0.z,a0.w,a1.x,a1.y,a1.z,a1.w};
            float rb[8] = {b0.x,b0.y,b0.z,b0.w,b1.x,b1.y,b1.z,b1.w};
            #pragma unroll
            for (int i = 0; i < 8; i++)
                #pragma unroll
                for (int j = 0; j < 8; j++)
                    c[i][j] = fmaf(ra[i], rb[j], c[i][j]);
        }
        __syncthreads();
    }

    #pragma unroll
    for (int i = 0; i < 8; i++) {
        int m = m0 + (ty<<2) + (i & 3) + ((i >> 2) << 6);
        #pragma unroll
        for (int j = 0; j < 8; j++) {
            int n = n0 + (tx<<2) + (j & 3) + ((j >> 2) << 6);
            float v = c[i][j] + bias[n];
            if (MODE == 1) {
                int bb = m >> 11;            // m / S
                int s  = m & (Sn - 1);
                int hh = n >> 6;             // n / D
                int d  = n & (Dn - 1);
                outq[(((bb << 4) + hh) * Sn + s) * Dn + d] = v;
            } else {
                outp[m * En + n] = v;
            }
        }
    }
}

// ---------------------------------------------------------------------------
// Flash attention: one CTA handles 64 query rows for one (b, h).
// 256 threads = 16x16 grid; each thread owns a 4x4 block of (row, col).
// Scores and PV are both register-blocked GEMMs through float4 smem reads.
// ---------------------------------------------------------------------------
#define ASTRIDE 68   // 64 + 4 pad (keeps float4 alignment, breaks bank aliasing)

__global__ __launch_bounds__(256)
void attn_kernel()
{
    extern __shared__ float sm[];
    float* QsT = sm;                    // [k=64][ASTRIDE] rows along minor
    float* KsT = QsT + 64*ASTRIDE;      // [k=64][ASTRIDE] keys along minor
    float* Vs  = KsT + 64*ASTRIDE;      // [j=64][ASTRIDE] d along minor
    float* PsT = Vs  + 64*ASTRIDE;      // [j=64][ASTRIDE] rows along minor
    float* mS  = PsT + 64*ASTRIDE;      // [64] mask flags

    const int tid = threadIdx.x;
    const int tx = tid & 15;
    const int ty = tid >> 4;
    const int qt = blockIdx.x;
    const int h  = blockIdx.y;
    const int b  = blockIdx.z;

    const float* Qg = g_Q + ((size_t)(b*Hn + h)*Sn + qt*64) * Dn;
    const float* Kg = g_K + (size_t)(b*Hn + h)*Sn*Dn;
    const float* Vg = g_V + (size_t)(b*Hn + h)*Sn*Dn;
    const float* mk = g_maskf + b*Sn;

    // Load Q tile transposed, pre-scaled by 1/sqrt(D)=0.125
    {
        int r  = tid >> 2;           // 0..63
        int c0 = (tid & 3) * 16;     // 0,16,32,48
        #pragma unroll
        for (int t = 0; t < 4; t++) {
            float4 v = *(const float4*)&Qg[r*Dn + c0 + t*4];
            QsT[(c0+t*4+0)*ASTRIDE + r] = v.x * 0.125f;
            QsT[(c0+t*4+1)*ASTRIDE + r] = v.y * 0.125f;
            QsT[(c0+t*4+2)*ASTRIDE + r] = v.z * 0.125f;
            QsT[(c0+t*4+3)*ASTRIDE + r] = v.w * 0.125f;
        }
    }

    float m_r[4], l_r[4], acc[4][4];
    #pragma unroll
    for (int i = 0; i < 4; i++) {
        m_r[i] = -INFINITY; l_r[i] = 0.f;
        #pragma unroll
        for (int j = 0; j < 4; j++) acc[i][j] = 0.f;
    }

    for (int kt = 0; kt < Sn/64; ++kt) {
        __syncthreads();   // prior-tile PV reads done before overwrite
        {
            int r  = tid >> 2;
            int c0 = (tid & 3) * 16;
            const float* Kt = Kg + (size_t)(kt*64 + r)*Dn;
            const float* Vt = Vg + (size_t)(kt*64 + r)*Dn;
            #pragma unroll
            for (int t = 0; t < 4; t++) {
                float4 kv = *(const float4*)&Kt[c0 + t*4];
                KsT[(c0+t*4+0)*ASTRIDE + r] = kv.x;
                KsT[(c0+t*4+1)*ASTRIDE + r] = kv.y;
                KsT[(c0+t*4+2)*ASTRIDE + r] = kv.z;
                KsT[(c0+t*4+3)*ASTRIDE + r] = kv.w;
                float4 vv = *(const float4*)&Vt[c0 + t*4];
                *(float4*)&Vs[r*ASTRIDE + c0 + t*4] = vv;
            }
            if (tid < 64) mS[tid] = mk[kt*64 + tid];
        }
        __syncthreads();

        // ---- scores: s[i][j] = (Q/8) . K  (64-deep dot) ----
        float s[4][4];
        #pragma unroll
        for (int i = 0; i < 4; i++)
            #pragma unroll
            for (int j = 0; j < 4; j++) s[i][j] = 0.f;

        #pragma unroll 8
        for (int k = 0; k < 64; k++) {
            float4 q4 = *(const float4*)&QsT[k*ASTRIDE + (ty<<2)];
            float4 k4 = *(const float4*)&KsT[k*ASTRIDE + (tx<<2)];
            float qa[4] = {q4.x, q4.y, q4.z, q4.w};
            float kb[4] = {k4.x, k4.y, k4.z, k4.w};
            #pragma unroll
            for (int i = 0; i < 4; i++)
                #pragma unroll
                for (int j = 0; j < 4; j++)
                    s[i][j] = fmaf(qa[i], kb[j], s[i][j]);
        }

        // ---- mask (exact -1e9 replacement, matching reference) ----
        #pragma unroll
        for (int j = 0; j < 4; j++) {
            float flag = mS[(tx<<2) + j];
            #pragma unroll
            for (int i = 0; i < 4; i++)
                s[i][j] = (flag != 0.f) ? -1e9f : s[i][j];
        }

        // ---- online softmax (row reduction across the 16 tx lanes) ----
        #pragma unroll
        for (int i = 0; i < 4; i++) {
            float mx = fmaxf(fmaxf(s[i][0], s[i][1]), fmaxf(s[i][2], s[i][3]));
            #pragma unroll
            for (int off = 8; off >= 1; off >>= 1)
                mx = fmaxf(mx, __shfl_xor_sync(0xffffffffu, mx, off, 16));
            float mnew = fmaxf(m_r[i], mx);
            float fs = __expf(m_r[i] - mnew);   // exp(-inf - finite) = 0 first tile
            float ps = 0.f;
            #pragma unroll
            for (int j = 0; j < 4; j++) {
                float p = __expf(s[i][j] - mnew);
                s[i][j] = p;
                ps += p;
            }
            #pragma unroll
            for (int off = 8; off >= 1; off >>= 1)
                ps += __shfl_xor_sync(0xffffffffu, ps, off, 16);
            l_r[i] = l_r[i]*fs + ps;
            m_r[i] = mnew;
            #pragma unroll
            for (int j = 0; j < 4; j++) acc[i][j] *= fs;
        }

        // ---- stage P transposed for the PV GEMM ----
        #pragma unroll
        for (int j = 0; j < 4; j++)
            *(float4*)&PsT[((tx<<2)+j)*ASTRIDE + (ty<<2)] =
                make_float4(s[0][j], s[1][j], s[2][j], s[3][j]);
        __syncthreads();

        // ---- PV: acc[i][c] += sum_j P[row_i][j] * V[j][d_c] ----
        #pragma unroll 8
        for (int j = 0; j < 64; j++) {
            float4 p4 = *(const float4*)&PsT[j*ASTRIDE + (ty<<2)];
            float4 v4 = *(const float4*)&Vs [j*ASTRIDE + (tx<<2)];
            float pa[4] = {p4.x, p4.y, p4.z, p4.w};
            float vb[4] = {v4.x, v4.y, v4.z, v4.w};
            #pragma unroll
            for (int i = 0; i < 4; i++)
                #pragma unroll
                for (int cjj = 0; cjj < 4; cjj++)
                    acc[i][cjj] = fmaf(pa[i], vb[cjj], acc[i][cjj]);
        }
    }

    // ---- epilogue: normalize and write in [B,S,E] layout for out-proj ----
    #pragma unroll
    for (int i = 0; i < 4; i++) {
        float inv = 1.f / l_r[i];
        int srow = qt*64 + (ty<<2) + i;
        float4 o = make_float4(acc[i][0]*inv, acc[i][1]*inv,
                               acc[i][2]*inv, acc[i][3]*inv);
        *(float4*)&g_A[((size_t)(b*Sn + srow))*En + h*Dn + (tx<<2)] = o;
    }
}

// ---------------------------------------------------------------------------
extern "C" void kernel_launch(void* const* d_in, const int* in_sizes, int n_in,
                              void* d_out, int out_size)
{
    const float* x  = (const float*)d_in[0];
    const unsigned char* mask = (const unsigned char*)d_in[1];  // dtype sniffed on device
    const float* Wq = (const float*)d_in[2];
    const float* bq = (const float*)d_in[3];
    const float* Wk = (const float*)d_in[4];
    const float* bk = (const float*)d_in[5];
    const float* Wv = (const float*)d_in[6];
    const float* bv = (const float*)d_in[7];
    const float* Wo = (const float*)d_in[8];
    const float* bo = (const float*)d_in[9];
    float* out = (float*)d_out;

    const int attn_smem = (4*64*ASTRIDE + 64) * (int)sizeof(float);  // ~69.9 KB
    cudaFuncSetAttribute(attn_kernel,
                         cudaFuncAttributeMaxDynamicSharedMemorySize, attn_smem);

    // Normalize the mask into g_maskf (dtype-agnostic)
    mask_prep<<<1, 256>>>(mask);

    // QKV projections (z = 0/1/2 -> Q/K/V), head-transposed epilogue
    gemm_kernel<1><<<dim3(En/128, Mn/128, 3), 256>>>(
        x, Wq, bq, Wk, bk, Wv, bv, nullptr);

    // Attention
    attn_kernel<<<dim3(Sn/64, Hn, Bn), 256, attn_smem>>>();

    // Output projection
    gemm_kernel<0><<<dim3(En/128, Mn/128, 1), 256>>>(
        nullptr, Wo, bo, nullptr, nullptr, nullptr, nullptr, out);
}

// round 8
// speedup vs baseline: 1.3967x; 1.3967x over previous
#include <cuda_runtime.h>
#include <math.h>
#include <cstdint>

// Problem constants
#define Bn 2
#define Sn 2048
#define En 1024
#define Hn 16
#define Dn 64
#define Mn (Bn*Sn)   // 4096 rows

// Scratch (static __device__ arrays: allocation-guard safe)
__device__ float g_Q[Bn*Hn*Sn*Dn];   // [B,H,S,D]
__device__ float g_K[Bn*Hn*Sn*Dn];
__device__ float g_V[Bn*Hn*Sn*Dn];
__device__ float g_A[Mn*En];         // attention output, [B,S,E]
__device__ float g_maskf[Bn*Sn];     // normalized mask: 1.0 = masked out

// ===========================================================================
// Mask prep (dtype sniff: uint8 / int32 / float32) — proven in R6
// ===========================================================================
__global__ void mask_prep(const unsigned char* __restrict__ m)
{
    __shared__ int s_cnt[2];
    const int tid = threadIdx.x;
    if (tid < 2) s_cnt[tid] = 0;
    __syncthreads();
    int c1 = 0, c0 = 0;
    for (int i = tid; i < (Bn*Sn)/4; i += blockDim.x) {
        uchar4 v = ((const uchar4*)m)[i];
        if (v.y) c1++;
        if (v.x) c0++;
    }
    atomicAdd(&s_cnt[0], c1);
    atomicAdd(&s_cnt[1], c0);
    __syncthreads();
    const int mode = (s_cnt[0] > 0) ? 0 : ((s_cnt[1] > 0) ? 1 : 2);
    for (int i = tid; i < Bn*Sn; i += blockDim.x) {
        float f;
        if (mode == 0)      f = m[i] ? 1.f : 0.f;
        else if (mode == 1) f = (((const int*)m)[i] != 0) ? 1.f : 0.f;
        else                f = (((const float*)m)[i] != 0.f) ? 1.f : 0.f;
        g_maskf[i] = f;
    }
}

// ===========================================================================
// Tensor-core GEMM via mma.sync m16n8k16 bf16, 3-pass split precision.
//   x = hi + lo (bf16 truncation split); C += Ah*Bh + Ah*Bl + Al*Bh.
// C[M,N] = A[M,K] * W[N,K]^T + bias. 128x128 tile, BK=32, 8 warps (32x64 each).
// MODE 1: QKV (blockIdx.z selects W/b), head-transposed writes to g_Q/K/V.
// MODE 0: out-projection from g_A -> outp.
// ===========================================================================
#define GK_STRIDE 36                  // bf16 row stride (32 + 4 pad)
#define PLANE (128*GK_STRIDE*2)       // 9216 B
#define AHI 0
#define ALO PLANE
#define BHI (2*PLANE)
#define BLO (3*PLANE)
#define STG (4*PLANE)                 // 36864 B per stage
#define GEMM_SMEM (2*STG)             // 73728 B

// split fp32 -> (hi bf16 bits, lo bf16 bits) by truncation
__device__ __forceinline__ void bsplit(float x, uint32_t& h, uint32_t& l) {
    uint32_t u = __float_as_uint(x);
    h = u >> 16;
    float lo = x - __uint_as_float(u & 0xFFFF0000u);
    l = __float_as_uint(lo) >> 16;
}

__device__ __forceinline__ void mma_bf16(float* c, uint32_t a0, uint32_t a1,
                                         uint32_t a2, uint32_t a3,
                                         uint32_t b0, uint32_t b1) {
    asm volatile(
        "mma.sync.aligned.m16n8k16.row.col.f32.bf16.bf16.f32 "
        "{%0,%1,%2,%3}, {%4,%5,%6,%7}, {%8,%9}, {%0,%1,%2,%3};"
        : "+f"(c[0]), "+f"(c[1]), "+f"(c[2]), "+f"(c[3])
        : "r"(a0), "r"(a1), "r"(a2), "r"(a3), "r"(b0), "r"(b1));
}

template<int MODE>
__global__ __launch_bounds__(256, 1)
void gemm_mma(const float* __restrict__ A,
              const float* __restrict__ W0, const float* __restrict__ bias0,
              const float* __restrict__ W1, const float* __restrict__ bias1,
              const float* __restrict__ W2, const float* __restrict__ bias2,
              float* __restrict__ outp)
{
    extern __shared__ char smem[];
    const int tid = threadIdx.x;
    const int wid = tid >> 5;
    const int lid = tid & 31;
    const int wm  = wid & 3;          // warp row: 32 rows each
    const int wn  = wid >> 2;         // warp col: 64 cols each
    const int m0 = blockIdx.y * 128;
    const int n0 = blockIdx.x * 128;

    const float* W    = W0;
    const float* bias = bias0;
    float* outq = nullptr;
    if (MODE == 1) {
        int z = blockIdx.z;
        W    = (z==0) ? W0    : ((z==1) ? W1    : W2);
        bias = (z==0) ? bias0 : ((z==1) ? bias1 : bias2);
        outq = (z==0) ? g_Q   : ((z==1) ? g_K   : g_V);
    }
    const float* Ap = (MODE == 1) ? A : g_A;

    // per-thread global-load geometry: 4 float4 per matrix per k-tile
    const int grow = tid >> 1;             // not used; keep layout below
    (void)grow;

    float c[2][8][4];
    #pragma unroll
    for (int mt = 0; mt < 2; mt++)
        #pragma unroll
        for (int nt = 0; nt < 8; nt++)
            #pragma unroll
            for (int r = 0; r < 4; r++) c[mt][nt][r] = 0.f;

    // fragment smem byte offsets (within a plane)
    const int qrow = lid >> 2;             // 0..7
    const int qk   = (lid & 3) * 2;        // 0,2,4,6
    const int aOff = ((wm*32 + qrow)*GK_STRIDE + qk) * 2;
    const int bOff = ((wn*64 + qrow)*GK_STRIDE + qk) * 2;

    float4 va[4], vb[4];
    // ---- preload k-tile 0 ----
    #pragma unroll
    for (int i = 0; i < 4; i++) {
        int f4 = tid + i*256;
        int row = f4 >> 3, c4 = f4 & 7;
        va[i] = *(const float4*)&Ap[(size_t)(m0 + row)*En + c4*4];
        vb[i] = *(const float4*)&W [(size_t)(n0 + row)*En + c4*4];
    }

    const int NKT = En / 32;
    for (int kt = 0; kt < NKT; kt++) {
        // ---- split + store current regs into stage kt&1 ----
        {
            char* stg = smem + (kt & 1) * STG;
            #pragma unroll
            for (int i = 0; i < 4; i++) {
                int f4 = tid + i*256;
                int row = f4 >> 3, c4 = f4 & 7;
                int off = (row*GK_STRIDE + c4*4) * 2;
                uint32_t h0,l0,h1,l1,h2,l2,h3,l3;
                bsplit(va[i].x, h0, l0); bsplit(va[i].y, h1, l1);
                bsplit(va[i].z, h2, l2); bsplit(va[i].w, h3, l3);
                *(uint2*)(stg + AHI + off) = make_uint2(h0|(h1<<16), h2|(h3<<16));
                *(uint2*)(stg + ALO + off) = make_uint2(l0|(l1<<16), l2|(l3<<16));
                bsplit(vb[i].x, h0, l0); bsplit(vb[i].y, h1, l1);
                bsplit(vb[i].z, h2, l2); bsplit(vb[i].w, h3, l3);
                *(uint2*)(stg + BHI + off) = make_uint2(h0|(h1<<16), h2|(h3<<16));
                *(uint2*)(stg + BLO + off) = make_uint2(l0|(l1<<16), l2|(l3<<16));
            }
        }
        __syncthreads();

        // ---- prefetch next k-tile into regs ----
        if (kt + 1 < NKT) {
            const int k0 = (kt + 1) * 32;
            #pragma unroll
            for (int i = 0; i < 4; i++) {
                int f4 = tid + i*256;
                int row = f4 >> 3, c4 = f4 & 7;
                va[i] = *(const float4*)&Ap[(size_t)(m0 + row)*En + k0 + c4*4];
                vb[i] = *(const float4*)&W [(size_t)(n0 + row)*En + k0 + c4*4];
            }
        }

        // ---- compute on stage kt&1: 3 passes x 2 k-steps ----
        const char* stg = smem + (kt & 1) * STG;
        #pragma unroll
        for (int ks = 0; ks < 2; ks++) {
            const int kb = ks * 32;        // 16 bf16 = 32 bytes along k
            uint32_t ah[2][4], al[2][4], bh[8][2], bl[8][2];
            #pragma unroll
            for (int mt = 0; mt < 2; mt++) {
                int base = aOff + mt*16*GK_STRIDE*2 + kb;
                #pragma unroll
                for (int r = 0; r < 4; r++) {
                    int o = base + (r & 1)*8*GK_STRIDE*2 + (r >> 1)*16;
                    ah[mt][r] = *(const uint32_t*)(stg + AHI + o);
                    al[mt][r] = *(const uint32_t*)(stg + ALO + o);
                }
            }
            #pragma unroll
            for (int nt = 0; nt < 8; nt++) {
                int base = bOff + nt*8*GK_STRIDE*2 + kb;
                #pragma unroll
                for (int r = 0; r < 2; r++) {
                    int o = base + r*16;
                    bh[nt][r] = *(const uint32_t*)(stg + BHI + o);
                    bl[nt][r] = *(const uint32_t*)(stg + BLO + o);
                }
            }
            #pragma unroll
            for (int mt = 0; mt < 2; mt++)
                #pragma unroll
                for (int nt = 0; nt < 8; nt++) {
                    mma_bf16(c[mt][nt], ah[mt][0], ah[mt][1], ah[mt][2], ah[mt][3],
                             bh[nt][0], bh[nt][1]);              // hi*hi
                    mma_bf16(c[mt][nt], ah[mt][0], ah[mt][1], ah[mt][2], ah[mt][3],
                             bl[nt][0], bl[nt][1]);              // hi*lo
                    mma_bf16(c[mt][nt], al[mt][0], al[mt][1], al[mt][2], al[mt][3],
                             bh[nt][0], bh[nt][1]);              // lo*hi
                }
        }
        if (kt + 1 < NKT) __syncthreads();
    }

    // ---- epilogue: bias + direct float2 stores ----
    #pragma unroll
    for (int mt = 0; mt < 2; mt++) {
        #pragma unroll
        for (int nt = 0; nt < 8; nt++) {
            int row = m0 + wm*32 + mt*16 + qrow;
            int col = n0 + wn*64 + nt*8 + (lid & 3)*2;
            float b0 = bias[col], b1 = bias[col + 1];
            float2 lo = make_float2(c[mt][nt][0] + b0, c[mt][nt][1] + b1);
            float2 hi = make_float2(c[mt][nt][2] + b0, c[mt][nt][3] + b1);
            if (MODE == 1) {
                int bb = row >> 11;
                int h  = col >> 6;
                int d  = col & 63;
                size_t base = ((size_t)(bb*Hn + h)*Sn) * Dn + d;
                *(float2*)&outq[base + (size_t)(row & (Sn-1))*Dn]       = lo;
                *(float2*)&outq[base + (size_t)((row & (Sn-1)) + 8)*Dn] = hi;
            } else {
                *(float2*)&outp[(size_t)row*En + col]       = lo;
                *(float2*)&outp[(size_t)(row + 8)*En + col] = hi;
            }
        }
    }
}

// ===========================================================================
// Flash attention (fp32, unchanged from R6-passing version)
// ===========================================================================
#define ASTRIDE 68

__global__ __launch_bounds__(256)
void attn_kernel()
{
    extern __shared__ float sm[];
    float* QsT = sm;
    float* KsT = QsT + 64*ASTRIDE;
    float* Vs  = KsT + 64*ASTRIDE;
    float* PsT = Vs  + 64*ASTRIDE;
    float* mS  = PsT + 64*ASTRIDE;

    const int tid = threadIdx.x;
    const int tx = tid & 15;
    const int ty = tid >> 4;
    const int qt = blockIdx.x;
    const int h  = blockIdx.y;
    const int b  = blockIdx.z;

    const float* Qg = g_Q + ((size_t)(b*Hn + h)*Sn + qt*64) * Dn;
    const float* Kg = g_K + (size_t)(b*Hn + h)*Sn*Dn;
    const float* Vg = g_V + (size_t)(b*Hn + h)*Sn*Dn;
    const float* mk = g_maskf + b*Sn;

    {
        int r  = tid >> 2;
        int c0 = (tid & 3) * 16;
        #pragma unroll
        for (int t = 0; t < 4; t++) {
            float4 v = *(const float4*)&Qg[r*Dn + c0 + t*4];
            QsT[(c0+t*4+0)*ASTRIDE + r] = v.x * 0.125f;
            QsT[(c0+t*4+1)*ASTRIDE + r] = v.y * 0.125f;
            QsT[(c0+t*4+2)*ASTRIDE + r] = v.z * 0.125f;
            QsT[(c0+t*4+3)*ASTRIDE + r] = v.w * 0.125f;
        }
    }

    float m_r[4], l_r[4], acc[4][4];
    #pragma unroll
    for (int i = 0; i < 4; i++) {
        m_r[i] = -INFINITY; l_r[i] = 0.f;
        #pragma unroll
        for (int j = 0; j < 4; j++) acc[i][j] = 0.f;
    }

    for (int kt = 0; kt < Sn/64; ++kt) {
        __syncthreads();
        {
            int r  = tid >> 2;
            int c0 = (tid & 3) * 16;
            const float* Kt = Kg + (size_t)(kt*64 + r)*Dn;
            const float* Vt = Vg + (size_t)(kt*64 + r)*Dn;
            #pragma unroll
            for (int t = 0; t < 4; t++) {
                float4 kv = *(const float4*)&Kt[c0 + t*4];
                KsT[(c0+t*4+0)*ASTRIDE + r] = kv.x;
                KsT[(c0+t*4+1)*ASTRIDE + r] = kv.y;
                KsT[(c0+t*4+2)*ASTRIDE + r] = kv.z;
                KsT[(c0+t*4+3)*ASTRIDE + r] = kv.w;
                float4 vv = *(const float4*)&Vt[c0 + t*4];
                *(float4*)&Vs[r*ASTRIDE + c0 + t*4] = vv;
            }
            if (tid < 64) mS[tid] = mk[kt*64 + tid];
        }
        __syncthreads();

        float s[4][4];
        #pragma unroll
        for (int i = 0; i < 4; i++)
            #pragma unroll
            for (int j = 0; j < 4; j++) s[i][j] = 0.f;

        #pragma unroll 8
        for (int k = 0; k < 64; k++) {
            float4 q4 = *(const float4*)&QsT[k*ASTRIDE + (ty<<2)];
            float4 k4 = *(const float4*)&KsT[k*ASTRIDE + (tx<<2)];
            float qa[4] = {q4.x, q4.y, q4.z, q4.w};
            float kb[4] = {k4.x, k4.y, k4.z, k4.w};
            #pragma unroll
            for (int i = 0; i < 4; i++)
                #pragma unroll
                for (int j = 0; j < 4; j++)
                    s[i][j] = fmaf(qa[i], kb[j], s[i][j]);
        }

        #pragma unroll
        for (int j = 0; j < 4; j++) {
            float flag = mS[(tx<<2) + j];
            #pragma unroll
            for (int i = 0; i < 4; i++)
                s[i][j] = (flag != 0.f) ? -1e9f : s[i][j];
        }

        #pragma unroll
        for (int i = 0; i < 4; i++) {
            float mx = fmaxf(fmaxf(s[i][0], s[i][1]), fmaxf(s[i][2], s[i][3]));
            #pragma unroll
            for (int off = 8; off >= 1; off >>= 1)
                mx = fmaxf(mx, __shfl_xor_sync(0xffffffffu, mx, off, 16));
            float mnew = fmaxf(m_r[i], mx);
            float fs = __expf(m_r[i] - mnew);
            float ps = 0.f;
            #pragma unroll
            for (int j = 0; j < 4; j++) {
                float p = __expf(s[i][j] - mnew);
                s[i][j] = p;
                ps += p;
            }
            #pragma unroll
            for (int off = 8; off >= 1; off >>= 1)
                ps += __shfl_xor_sync(0xffffffffu, ps, off, 16);
            l_r[i] = l_r[i]*fs + ps;
            m_r[i] = mnew;
            #pragma unroll
            for (int j = 0; j < 4; j++) acc[i][j] *= fs;
        }

        #pragma unroll
        for (int j = 0; j < 4; j++)
            *(float4*)&PsT[((tx<<2)+j)*ASTRIDE + (ty<<2)] =
                make_float4(s[0][j], s[1][j], s[2][j], s[3][j]);
        __syncthreads();

        #pragma unroll 8
        for (int j = 0; j < 64; j++) {
            float4 p4 = *(const float4*)&PsT[j*ASTRIDE + (ty<<2)];
            float4 v4 = *(const float4*)&Vs [j*ASTRIDE + (tx<<2)];
            float pa[4] = {p4.x, p4.y, p4.z, p4.w};
            float vb[4] = {v4.x, v4.y, v4.z, v4.w};
            #pragma unroll
            for (int i = 0; i < 4; i++)
                #pragma unroll
                for (int cjj = 0; cjj < 4; cjj++)
                    acc[i][cjj] = fmaf(pa[i], vb[cjj], acc[i][cjj]);
        }
    }

    #pragma unroll
    for (int i = 0; i < 4; i++) {
        float inv = 1.f / l_r[i];
        int srow = qt*64 + (ty<<2) + i;
        float4 o = make_float4(acc[i][0]*inv, acc[i][1]*inv,
                               acc[i][2]*inv, acc[i][3]*inv);
        *(float4*)&g_A[((size_t)(b*Sn + srow))*En + h*Dn + (tx<<2)] = o;
    }
}

// ---------------------------------------------------------------------------
extern "C" void kernel_launch(void* const* d_in, const int* in_sizes, int n_in,
                              void* d_out, int out_size)
{
    const float* x  = (const float*)d_in[0];
    const unsigned char* mask = (const unsigned char*)d_in[1];
    const float* Wq = (const float*)d_in[2];
    const float* bq = (const float*)d_in[3];
    const float* Wk = (const float*)d_in[4];
    const float* bk = (const float*)d_in[5];
    const float* Wv = (const float*)d_in[6];
    const float* bv = (const float*)d_in[7];
    const float* Wo = (const float*)d_in[8];
    const float* bo = (const float*)d_in[9];
    float* out = (float*)d_out;

    const int attn_smem = (4*64*ASTRIDE + 64) * (int)sizeof(float);
    cudaFuncSetAttribute(attn_kernel,
                         cudaFuncAttributeMaxDynamicSharedMemorySize, attn_smem);
    cudaFuncSetAttribute(gemm_mma<1>,
                         cudaFuncAttributeMaxDynamicSharedMemorySize, GEMM_SMEM);
    cudaFuncSetAttribute(gemm_mma<0>,
                         cudaFuncAttributeMaxDynamicSharedMemorySize, GEMM_SMEM);

    mask_prep<<<1, 256>>>(mask);

    // QKV projections on tensor cores (z = 0/1/2 -> Q/K/V)
    gemm_mma<1><<<dim3(En/128, Mn/128, 3), 256, GEMM_SMEM>>>(
        x, Wq, bq, Wk, bk, Wv, bv, nullptr);

    attn_kernel<<<dim3(Sn/64, Hn, Bn), 256, attn_smem>>>();

    // Output projection on tensor cores
    gemm_mma<0><<<dim3(En/128, Mn/128, 1), 256, GEMM_SMEM>>>(
        nullptr, Wo, bo, nullptr, nullptr, nullptr, nullptr, out);
}

// round 10
// speedup vs baseline: 2.7331x; 1.9568x over previous
#include <cuda_runtime.h>
#include <math.h>
#include <cstdint>

typedef uint32_t u32;

// Problem constants
#define Bn 2
#define Sn 2048
#define En 1024
#define Hn 16
#define Dn 64
#define Mn (Bn*Sn)   // 4096 rows

// Scratch (static __device__ arrays: allocation-guard safe)
__device__ float g_Q[Bn*Hn*Sn*Dn];   // [B,H,S,D]
__device__ float g_K[Bn*Hn*Sn*Dn];
__device__ float g_V[Bn*Hn*Sn*Dn];
__device__ float g_A[Mn*En];         // attention output, [B,S,E]
__device__ float g_maskf[Bn*Sn];     // normalized mask: 1.0 = masked out
// bf16 split copies for tensor-core attention
__device__ unsigned short g_Kbh[Bn*Hn*Sn*Dn];  // [B,H,S,D] hi
__device__ unsigned short g_Kbl[Bn*Hn*Sn*Dn];  // [B,H,S,D] lo
__device__ unsigned short g_Vth[Bn*Hn*Dn*Sn];  // [B,H,D,S] hi (transposed)
__device__ unsigned short g_Vtl[Bn*Hn*Dn*Sn];  // [B,H,D,S] lo

// ===========================================================================
// helpers
// ===========================================================================
__device__ __forceinline__ void bsplit(float x, u32& h, u32& l) {
    u32 u = __float_as_uint(x);
    h = u >> 16;
    float lo = x - __uint_as_float(u & 0xFFFF0000u);
    l = __float_as_uint(lo) >> 16;
}
// split two floats -> packed hi bf16x2, packed lo bf16x2
__device__ __forceinline__ void psplit2(float x, float y, u32& hp, u32& lp) {
    u32 ux = __float_as_uint(x), uy = __float_as_uint(y);
    float xl = x - __uint_as_float(ux & 0xFFFF0000u);
    float yl = y - __uint_as_float(uy & 0xFFFF0000u);
    hp = (ux >> 16) | (uy & 0xFFFF0000u);
    lp = (__float_as_uint(xl) >> 16) | (__float_as_uint(yl) & 0xFFFF0000u);
}
__device__ __forceinline__ void mma_bf16(float* c, u32 a0, u32 a1,
                                         u32 a2, u32 a3, u32 b0, u32 b1) {
    asm volatile(
        "mma.sync.aligned.m16n8k16.row.col.f32.bf16.bf16.f32 "
        "{%0,%1,%2,%3}, {%4,%5,%6,%7}, {%8,%9}, {%0,%1,%2,%3};"
        : "+f"(c[0]), "+f"(c[1]), "+f"(c[2]), "+f"(c[3])
        : "r"(a0), "r"(a1), "r"(a2), "r"(a3), "r"(b0), "r"(b1));
}
__device__ __forceinline__ u32 smem_u32(const void* p) {
    u32 a;
    asm("{ .reg .u64 t; cvta.to.shared.u64 t, %1; cvt.u32.u64 %0, t; }"
        : "=r"(a) : "l"(p));
    return a;
}
#define CP_ASYNC16(dst, src) \
    asm volatile("cp.async.cg.shared.global [%0], [%1], 16;" \
                 :: "r"(dst), "l"(src) : "memory")
#define CP_COMMIT() asm volatile("cp.async.commit_group;" ::: "memory")
#define CP_WAIT0()  asm volatile("cp.async.wait_group 0;" ::: "memory")

// ===========================================================================
// Mask prep (dtype sniff: uint8 / int32 / float32) — proven
// ===========================================================================
__global__ void mask_prep(const unsigned char* __restrict__ m)
{
    __shared__ int s_cnt[2];
    const int tid = threadIdx.x;
    if (tid < 2) s_cnt[tid] = 0;
    __syncthreads();
    int c1 = 0, c0 = 0;
    for (int i = tid; i < (Bn*Sn)/4; i += blockDim.x) {
        uchar4 v = ((const uchar4*)m)[i];
        if (v.y) c1++;
        if (v.x) c0++;
    }
    atomicAdd(&s_cnt[0], c1);
    atomicAdd(&s_cnt[1], c0);
    __syncthreads();
    const int mode = (s_cnt[0] > 0) ? 0 : ((s_cnt[1] > 0) ? 1 : 2);
    for (int i = tid; i < Bn*Sn; i += blockDim.x) {
        float f;
        if (mode == 0)      f = m[i] ? 1.f : 0.f;
        else if (mode == 1) f = (((const int*)m)[i] != 0) ? 1.f : 0.f;
        else                f = (((const float*)m)[i] != 0.f) ? 1.f : 0.f;
        g_maskf[i] = f;
    }
}

// ===========================================================================
// KV prep: split K -> bf16 hi/lo [B,H,S,D]; V -> transposed bf16 hi/lo [B,H,D,S]
// grid (S/32, H, B), 256 threads
// ===========================================================================
__global__ __launch_bounds__(256)
void kv_prep()
{
    __shared__ float vt[32][65];
    const int tid = threadIdx.x;
    const int bh = blockIdx.z * Hn + blockIdx.y;
    const int s0 = blockIdx.x * 32;
    const float* Ks = g_K + ((size_t)bh*Sn + s0)*Dn;
    const float* Vs = g_V + ((size_t)bh*Sn + s0)*Dn;

    #pragma unroll
    for (int i = 0; i < 2; i++) {
        int f4 = tid + (i << 8);
        int row = f4 >> 4, dim = (f4 & 15) * 4;
        float4 v = *(const float4*)&Ks[row*Dn + dim];
        u32 h0,l0,h1,l1,h2,l2,h3,l3;
        bsplit(v.x,h0,l0); bsplit(v.y,h1,l1); bsplit(v.z,h2,l2); bsplit(v.w,h3,l3);
        size_t o = ((size_t)bh*Sn + s0 + row)*Dn + dim;
        *(uint2*)&g_Kbh[o] = make_uint2(h0|(h1<<16), h2|(h3<<16));
        *(uint2*)&g_Kbl[o] = make_uint2(l0|(l1<<16), l2|(l3<<16));
        float4 w = *(const float4*)&Vs[row*Dn + dim];
        vt[row][dim] = w.x; vt[row][dim+1] = w.y;
        vt[row][dim+2] = w.z; vt[row][dim+3] = w.w;
    }
    __syncthreads();
    #pragma unroll
    for (int i = 0; i < 4; i++) {
        int u = tid + (i << 8);
        int d = u >> 4, j = u & 15;
        float v0 = vt[2*j][d], v1 = vt[2*j+1][d];
        u32 h0,l0,h1,l1;
        bsplit(v0,h0,l0); bsplit(v1,h1,l1);
        size_t o = ((size_t)bh*Dn + d)*Sn + s0 + 2*j;
        *(u32*)&g_Vth[o] = h0 | (h1<<16);
        *(u32*)&g_Vtl[o] = l0 | (l1<<16);
    }
}

// ===========================================================================
// Tensor-core GEMM (unchanged from R8, passing)
// ===========================================================================
#define GK_STRIDE 36
#define PLANE (128*GK_STRIDE*2)
#define AHI 0
#define ALO PLANE
#define BHI (2*PLANE)
#define BLO (3*PLANE)
#define STG (4*PLANE)
#define GEMM_SMEM (2*STG)

template<int MODE>
__global__ __launch_bounds__(256, 1)
void gemm_mma(const float* __restrict__ A,
              const float* __restrict__ W0, const float* __restrict__ bias0,
              const float* __restrict__ W1, const float* __restrict__ bias1,
              const float* __restrict__ W2, const float* __restrict__ bias2,
              float* __restrict__ outp)
{
    extern __shared__ char smem[];
    const int tid = threadIdx.x;
    const int wid = tid >> 5;
    const int lid = tid & 31;
    const int wm  = wid & 3;
    const int wn  = wid >> 2;
    const int m0 = blockIdx.y * 128;
    const int n0 = blockIdx.x * 128;

    const float* W    = W0;
    const float* bias = bias0;
    float* outq = nullptr;
    if (MODE == 1) {
        int z = blockIdx.z;
        W    = (z==0) ? W0    : ((z==1) ? W1    : W2);
        bias = (z==0) ? bias0 : ((z==1) ? bias1 : bias2);
        outq = (z==0) ? g_Q   : ((z==1) ? g_K   : g_V);
    }
    const float* Ap = (MODE == 1) ? A : g_A;

    float c[2][8][4];
    #pragma unroll
    for (int mt = 0; mt < 2; mt++)
        #pragma unroll
        for (int nt = 0; nt < 8; nt++)
            #pragma unroll
            for (int r = 0; r < 4; r++) c[mt][nt][r] = 0.f;

    const int qrow = lid >> 2;
    const int aOff = ((wm*32 + qrow)*GK_STRIDE + (lid & 3)*2) * 2;
    const int bOff = ((wn*64 + qrow)*GK_STRIDE + (lid & 3)*2) * 2;

    float4 va[4], vb[4];
    #pragma unroll
    for (int i = 0; i < 4; i++) {
        int f4 = tid + i*256;
        int row = f4 >> 3, c4 = f4 & 7;
        va[i] = *(const float4*)&Ap[(size_t)(m0 + row)*En + c4*4];
        vb[i] = *(const float4*)&W [(size_t)(n0 + row)*En + c4*4];
    }

    const int NKT = En / 32;
    for (int kt = 0; kt < NKT; kt++) {
        {
            char* stg = smem + (kt & 1) * STG;
            #pragma unroll
            for (int i = 0; i < 4; i++) {
                int f4 = tid + i*256;
                int row = f4 >> 3, c4 = f4 & 7;
                int off = (row*GK_STRIDE + c4*4) * 2;
                u32 h0,l0,h1,l1,h2,l2,h3,l3;
                bsplit(va[i].x, h0, l0); bsplit(va[i].y, h1, l1);
                bsplit(va[i].z, h2, l2); bsplit(va[i].w, h3, l3);
                *(uint2*)(stg + AHI + off) = make_uint2(h0|(h1<<16), h2|(h3<<16));
                *(uint2*)(stg + ALO + off) = make_uint2(l0|(l1<<16), l2|(l3<<16));
                bsplit(vb[i].x, h0, l0); bsplit(vb[i].y, h1, l1);
                bsplit(vb[i].z, h2, l2); bsplit(vb[i].w, h3, l3);
                *(uint2*)(stg + BHI + off) = make_uint2(h0|(h1<<16), h2|(h3<<16));
                *(uint2*)(stg + BLO + off) = make_uint2(l0|(l1<<16), l2|(l3<<16));
            }
        }
        __syncthreads();

        if (kt + 1 < NKT) {
            const int k0 = (kt + 1) * 32;
            #pragma unroll
            for (int i = 0; i < 4; i++) {
                int f4 = tid + i*256;
                int row = f4 >> 3, c4 = f4 & 7;
                va[i] = *(const float4*)&Ap[(size_t)(m0 + row)*En + k0 + c4*4];
                vb[i] = *(const float4*)&W [(size_t)(n0 + row)*En + k0 + c4*4];
            }
        }

        const char* stg = smem + (kt & 1) * STG;
        #pragma unroll
        for (int ks = 0; ks < 2; ks++) {
            const int kb = ks * 32;
            u32 ah[2][4], al[2][4], bh[8][2], bl[8][2];
            #pragma unroll
            for (int mt = 0; mt < 2; mt++) {
                int base = aOff + mt*16*GK_STRIDE*2 + kb;
                #pragma unroll
                for (int r = 0; r < 4; r++) {
                    int o = base + (r & 1)*8*GK_STRIDE*2 + (r >> 1)*16;
                    ah[mt][r] = *(const u32*)(stg + AHI + o);
                    al[mt][r] = *(const u32*)(stg + ALO + o);
                }
            }
            #pragma unroll
            for (int nt = 0; nt < 8; nt++) {
                int base = bOff + nt*8*GK_STRIDE*2 + kb;
                #pragma unroll
                for (int r = 0; r < 2; r++) {
                    int o = base + r*16;
                    bh[nt][r] = *(const u32*)(stg + BHI + o);
                    bl[nt][r] = *(const u32*)(stg + BLO + o);
                }
            }
            #pragma unroll
            for (int mt = 0; mt < 2; mt++)
                #pragma unroll
                for (int nt = 0; nt < 8; nt++) {
                    mma_bf16(c[mt][nt], ah[mt][0], ah[mt][1], ah[mt][2], ah[mt][3],
                             bh[nt][0], bh[nt][1]);
                    mma_bf16(c[mt][nt], ah[mt][0], ah[mt][1], ah[mt][2], ah[mt][3],
                             bl[nt][0], bl[nt][1]);
                    mma_bf16(c[mt][nt], al[mt][0], al[mt][1], al[mt][2], al[mt][3],
                             bh[nt][0], bh[nt][1]);
                }
        }
        if (kt + 1 < NKT) __syncthreads();
    }

    #pragma unroll
    for (int mt = 0; mt < 2; mt++) {
        #pragma unroll
        for (int nt = 0; nt < 8; nt++) {
            int row = m0 + wm*32 + mt*16 + qrow;
            int col = n0 + wn*64 + nt*8 + (lid & 3)*2;
            float b0 = bias[col], b1 = bias[col + 1];
            float2 lo = make_float2(c[mt][nt][0] + b0, c[mt][nt][1] + b1);
            float2 hi = make_float2(c[mt][nt][2] + b0, c[mt][nt][3] + b1);
            if (MODE == 1) {
                int bb = row >> 11;
                int h  = col >> 6;
                int d  = col & 63;
                size_t base = ((size_t)(bb*Hn + h)*Sn) * Dn + d;
                *(float2*)&outq[base + (size_t)(row & (Sn-1))*Dn]       = lo;
                *(float2*)&outq[base + (size_t)((row & (Sn-1)) + 8)*Dn] = hi;
            } else {
                *(float2*)&outp[(size_t)row*En + col]       = lo;
                *(float2*)&outp[(size_t)(row + 8)*En + col] = hi;
            }
        }
    }
}

// ===========================================================================
// Tensor-core flash attention. CTA = 128 q-rows of one (b,h); 8 warps x 16 rows.
// Key tile 128, cp.async double-buffered bf16 K/V from kv_prep outputs.
// QK^T and PV both 3-pass bf16 split on mma.sync.
// ===========================================================================
#define SQB 144                 // Q/K smem row stride bytes (72 bf16)
#define SVB 272                 // VT row stride bytes (136 bf16)
#define OFF_QL   18432
#define OFF_STAGE 36864
#define AKL   18432             // within stage: K lo
#define AVH   36864             // within stage: V hi
#define AVL   54272             // within stage: V lo
#define STAGE_SZ 71680
#define OFF_MS (OFF_STAGE + 2*STAGE_SZ)   // 180224
#define ATT_SMEM (OFF_MS + 1024)          // 181248

__global__ __launch_bounds__(256, 1)
void attn_tc()
{
    extern __shared__ char sm[];
    const u32 sb = smem_u32(sm);
    const int tid = threadIdx.x;
    const int wid = tid >> 5, lid = tid & 31;
    const int qr = lid >> 2, qc = lid & 3;
    const int qt = blockIdx.x, h = blockIdx.y, b = blockIdx.z;
    const int bh = b*Hn + h;

    const float* Qg = g_Q + ((size_t)bh*Sn + qt*128)*Dn;
    const float* mk = g_maskf + b*Sn;
    const unsigned short* Khg = g_Kbh + (size_t)bh*Sn*Dn;
    const unsigned short* Klg = g_Kbl + (size_t)bh*Sn*Dn;
    const unsigned short* Vhg = g_Vth + (size_t)bh*Dn*Sn;
    const unsigned short* Vlg = g_Vtl + (size_t)bh*Dn*Sn;
    float* mS = (float*)(sm + OFF_MS);

    // ---- Q load + 0.125 scale + split into smem (persistent) ----
    #pragma unroll
    for (int i = 0; i < 8; i++) {
        int f4 = tid + (i << 8);
        int row = f4 >> 4, dim = (f4 & 15) << 2;
        float4 v = *(const float4*)&Qg[row*Dn + dim];
        v.x *= 0.125f; v.y *= 0.125f; v.z *= 0.125f; v.w *= 0.125f;
        u32 h0,l0,h1,l1,h2,l2,h3,l3;
        bsplit(v.x,h0,l0); bsplit(v.y,h1,l1); bsplit(v.z,h2,l2); bsplit(v.w,h3,l3);
        *(uint2*)(sm + row*SQB + dim*2)          = make_uint2(h0|(h1<<16), h2|(h3<<16));
        *(uint2*)(sm + OFF_QL + row*SQB + dim*2) = make_uint2(l0|(l1<<16), l2|(l3<<16));
    }

    // ---- async tile loader: 4096 x 16B chunks (K hi/lo + V hi/lo) ----
    auto issue = [&](int kt, int st) {
        const u32 stg = sb + OFF_STAGE + st*STAGE_SZ;
        #pragma unroll
        for (int i = 0; i < 16; i++) {
            int c = tid + (i << 8);
            if (c < 2048) {
                int pl = c >> 10, row = (c >> 3) & 127, col = c & 7;
                const unsigned short* src = (pl ? Klg : Khg)
                    + (size_t)(kt*128 + row)*Dn + col*8;
                CP_ASYNC16(stg + pl*AKL + row*SQB + col*16, src);
            } else {
                int c2 = c - 2048;
                int pl = c2 >> 10, d = (c2 >> 4) & 63, col = c2 & 15;
                const unsigned short* src = (pl ? Vlg : Vhg)
                    + (size_t)d*Sn + kt*128 + col*8;
                CP_ASYNC16(stg + AVH + pl*(AVL-AVH) + d*SVB + col*16, src);
            }
        }
        if (tid < 128) mS[st*128 + tid] = mk[kt*128 + tid];
        CP_COMMIT();
    };

    float m0 = -INFINITY, m1 = -INFINITY, l0 = 0.f, l1 = 0.f;
    float acc[8][4];
    #pragma unroll
    for (int nt = 0; nt < 8; nt++)
        #pragma unroll
        for (int r = 0; r < 4; r++) acc[nt][r] = 0.f;

    issue(0, 0);

    const int aBase = (wid*16 + qr)*SQB + qc*4;

    for (int kt = 0; kt < Sn/128; kt++) {
        const int st = kt & 1;
        CP_WAIT0();
        __syncthreads();
        if (kt + 1 < Sn/128) issue(kt + 1, 1 - st);

        const char* KH = sm + OFF_STAGE + st*STAGE_SZ;
        const char* KL = KH + AKL;
        const char* VH = KH + AVH;
        const char* VL = KH + AVL;

        // ---- QK^T: scores [16 x 128] per warp ----
        float sc[16][4];
        #pragma unroll
        for (int nt = 0; nt < 16; nt++)
            #pragma unroll
            for (int r = 0; r < 4; r++) sc[nt][r] = 0.f;

        #pragma unroll
        for (int ks = 0; ks < 4; ks++) {
            const int ao = aBase + ks*32;
            u32 ah[4], al[4];
            ah[0] = *(const u32*)(sm + ao);
            ah[1] = *(const u32*)(sm + ao + 8*SQB);
            ah[2] = *(const u32*)(sm + ao + 16);
            ah[3] = *(const u32*)(sm + ao + 8*SQB + 16);
            al[0] = *(const u32*)(sm + OFF_QL + ao);
            al[1] = *(const u32*)(sm + OFF_QL + ao + 8*SQB);
            al[2] = *(const u32*)(sm + OFF_QL + ao + 16);
            al[3] = *(const u32*)(sm + OFF_QL + ao + 8*SQB + 16);
            #pragma unroll
            for (int nt = 0; nt < 16; nt++) {
                int bo = (nt*8 + qr)*SQB + qc*4 + ks*32;
                u32 bh0 = *(const u32*)(KH + bo), bh1 = *(const u32*)(KH + bo + 16);
                u32 bl0 = *(const u32*)(KL + bo), bl1 = *(const u32*)(KL + bo + 16);
                mma_bf16(sc[nt], ah[0], ah[1], ah[2], ah[3], bh0, bh1);
                mma_bf16(sc[nt], ah[0], ah[1], ah[2], ah[3], bl0, bl1);
                mma_bf16(sc[nt], al[0], al[1], al[2], al[3], bh0, bh1);
            }
        }

        // ---- mask ----
        const float* msk = mS + st*128;
        #pragma unroll
        for (int nt = 0; nt < 16; nt++) {
            int c0 = nt*8 + qc*2;
            if (msk[c0]   != 0.f) { sc[nt][0] = -1e9f; sc[nt][2] = -1e9f; }
            if (msk[c0+1] != 0.f) { sc[nt][1] = -1e9f; sc[nt][3] = -1e9f; }
        }

        // ---- online softmax (rows r and r+8; reduce over 4-lane quad) ----
        float mx0 = -INFINITY, mx1 = -INFINITY;
        #pragma unroll
        for (int nt = 0; nt < 16; nt++) {
            mx0 = fmaxf(mx0, fmaxf(sc[nt][0], sc[nt][1]));
            mx1 = fmaxf(mx1, fmaxf(sc[nt][2], sc[nt][3]));
        }
        mx0 = fmaxf(mx0, __shfl_xor_sync(0xffffffffu, mx0, 1));
        mx0 = fmaxf(mx0, __shfl_xor_sync(0xffffffffu, mx0, 2));
        mx1 = fmaxf(mx1, __shfl_xor_sync(0xffffffffu, mx1, 1));
        mx1 = fmaxf(mx1, __shfl_xor_sync(0xffffffffu, mx1, 2));
        float mn0 = fmaxf(m0, mx0), mn1 = fmaxf(m1, mx1);
        float fs0 = __expf(m0 - mn0), fs1 = __expf(m1 - mn1);
        m0 = mn0; m1 = mn1;

        float ps0 = 0.f, ps1 = 0.f;
        #pragma unroll
        for (int nt = 0; nt < 16; nt++) {
            float p0 = __expf(sc[nt][0] - mn0);
            float p1 = __expf(sc[nt][1] - mn0);
            float p2 = __expf(sc[nt][2] - mn1);
            float p3 = __expf(sc[nt][3] - mn1);
            ps0 += p0 + p1; ps1 += p2 + p3;
            sc[nt][0] = p0; sc[nt][1] = p1; sc[nt][2] = p2; sc[nt][3] = p3;
        }
        ps0 += __shfl_xor_sync(0xffffffffu, ps0, 1);
        ps0 += __shfl_xor_sync(0xffffffffu, ps0, 2);
        ps1 += __shfl_xor_sync(0xffffffffu, ps1, 1);
        ps1 += __shfl_xor_sync(0xffffffffu, ps1, 2);
        l0 = l0*fs0 + ps0;
        l1 = l1*fs1 + ps1;

        #pragma unroll
        for (int nt = 0; nt < 8; nt++) {
            acc[nt][0] *= fs0; acc[nt][1] *= fs0;
            acc[nt][2] *= fs1; acc[nt][3] *= fs1;
        }

        // ---- PV: P [16x128] x V [128x64], in two key-halves ----
        #pragma unroll
        for (int hf = 0; hf < 2; hf++) {
            u32 pah[4][4], pal[4][4];
            #pragma unroll
            for (int ksl = 0; ksl < 4; ksl++) {
                int kp = hf*4 + ksl;
                psplit2(sc[2*kp][0],   sc[2*kp][1],   pah[ksl][0], pal[ksl][0]);
                psplit2(sc[2*kp][2],   sc[2*kp][3],   pah[ksl][1], pal[ksl][1]);
                psplit2(sc[2*kp+1][0], sc[2*kp+1][1], pah[ksl][2], pal[ksl][2]);
                psplit2(sc[2*kp+1][2], sc[2*kp+1][3], pah[ksl][3], pal[ksl][3]);
            }
            #pragma unroll
            for (int ksl = 0; ksl < 4; ksl++) {
                int ks = hf*4 + ksl;
                #pragma unroll
                for (int nt = 0; nt < 8; nt++) {
                    int vo = (nt*8 + qr)*SVB + qc*4 + ks*32;
                    u32 vh0 = *(const u32*)(VH + vo), vh1 = *(const u32*)(VH + vo + 16);
                    u32 vl0 = *(const u32*)(VL + vo), vl1 = *(const u32*)(VL + vo + 16);
                    mma_bf16(acc[nt], pah[ksl][0], pah[ksl][1], pah[ksl][2], pah[ksl][3],
                             vh0, vh1);
                    mma_bf16(acc[nt], pal[ksl][0], pal[ksl][1], pal[ksl][2], pal[ksl][3],
                             vh0, vh1);
                    mma_bf16(acc[nt], pah[ksl][0], pah[ksl][1], pah[ksl][2], pah[ksl][3],
                             vl0, vl1);
                }
            }
        }
    }

    // ---- epilogue: normalize, write [B,S,E] ----
    float inv0 = 1.f / l0, inv1 = 1.f / l1;
    int row0 = qt*128 + wid*16 + qr;
    #pragma unroll
    for (int nt = 0; nt < 8; nt++) {
        int d = h*64 + nt*8 + qc*2;
        *(float2*)&g_A[((size_t)(b*Sn + row0))*En + d] =
            make_float2(acc[nt][0]*inv0, acc[nt][1]*inv0);
        *(float2*)&g_A[((size_t)(b*Sn + row0 + 8))*En + d] =
            make_float2(acc[nt][2]*inv1, acc[nt][3]*inv1);
    }
}

// ---------------------------------------------------------------------------
extern "C" void kernel_launch(void* const* d_in, const int* in_sizes, int n_in,
                              void* d_out, int out_size)
{
    const float* x  = (const float*)d_in[0];
    const unsigned char* mask = (const unsigned char*)d_in[1];
    const float* Wq = (const float*)d_in[2];
    const float* bq = (const float*)d_in[3];
    const float* Wk = (const float*)d_in[4];
    const float* bk = (const float*)d_in[5];
    const float* Wv = (const float*)d_in[6];
    const float* bv = (const float*)d_in[7];
    const float* Wo = (const float*)d_in[8];
    const float* bo = (const float*)d_in[9];
    float* out = (float*)d_out;

    cudaFuncSetAttribute(gemm_mma<1>,
                         cudaFuncAttributeMaxDynamicSharedMemorySize, GEMM_SMEM);
    cudaFuncSetAttribute(gemm_mma<0>,
                         cudaFuncAttributeMaxDynamicSharedMemorySize, GEMM_SMEM);
    cudaFuncSetAttribute(attn_tc,
                         cudaFuncAttributeMaxDynamicSharedMemorySize, ATT_SMEM);

    mask_prep<<<1, 256>>>(mask);

    gemm_mma<1><<<dim3(En/128, Mn/128, 3), 256, GEMM_SMEM>>>(
        x, Wq, bq, Wk, bk, Wv, bv, nullptr);

    kv_prep<<<dim3(Sn/32, Hn, Bn), 256>>>();

    attn_tc<<<dim3(Sn/128, Hn, Bn), 256, ATT_SMEM>>>();

    gemm_mma<0><<<dim3(En/128, Mn/128, 1), 256, GEMM_SMEM>>>(
        nullptr, Wo, bo, nullptr, nullptr, nullptr, nullptr, out);
}

// round 11
// speedup vs baseline: 3.1101x; 1.1380x over previous
#include <cuda_runtime.h>
#include <math.h>
#include <cstdint>

typedef uint32_t u32;

// Problem constants
#define Bn 2
#define Sn 2048
#define En 1024
#define Hn 16
#define Dn 64
#define Mn (Bn*Sn)   // 4096 rows

// Scratch (static __device__ arrays: allocation-guard safe)
__device__ float g_Q[Bn*Hn*Sn*Dn];   // [B,H,S,D]
__device__ float g_K[Bn*Hn*Sn*Dn];
__device__ float g_V[Bn*Hn*Sn*Dn];
__device__ float g_A[Mn*En];         // attention output, [B,S,E]
__device__ float g_maskf[Bn*Sn];     // normalized mask: 1.0 = masked out
// bf16 split copies for tensor-core attention
__device__ unsigned short g_Kbh[Bn*Hn*Sn*Dn];  // [B,H,S,D] hi
__device__ unsigned short g_Kbl[Bn*Hn*Sn*Dn];  // [B,H,S,D] lo
__device__ unsigned short g_Vth[Bn*Hn*Dn*Sn];  // [B,H,D,S] hi (transposed)
__device__ unsigned short g_Vtl[Bn*Hn*Dn*Sn];  // [B,H,D,S] lo

// ===========================================================================
// helpers
// ===========================================================================
__device__ __forceinline__ void bsplit(float x, u32& h, u32& l) {
    u32 u = __float_as_uint(x);
    h = u >> 16;
    float lo = x - __uint_as_float(u & 0xFFFF0000u);
    l = __float_as_uint(lo) >> 16;
}
__device__ __forceinline__ void psplit2(float x, float y, u32& hp, u32& lp) {
    u32 ux = __float_as_uint(x), uy = __float_as_uint(y);
    float xl = x - __uint_as_float(ux & 0xFFFF0000u);
    float yl = y - __uint_as_float(uy & 0xFFFF0000u);
    hp = (ux >> 16) | (uy & 0xFFFF0000u);
    lp = (__float_as_uint(xl) >> 16) | (__float_as_uint(yl) & 0xFFFF0000u);
}
__device__ __forceinline__ void mma_bf16(float* c, u32 a0, u32 a1,
                                         u32 a2, u32 a3, u32 b0, u32 b1) {
    asm volatile(
        "mma.sync.aligned.m16n8k16.row.col.f32.bf16.bf16.f32 "
        "{%0,%1,%2,%3}, {%4,%5,%6,%7}, {%8,%9}, {%0,%1,%2,%3};"
        : "+f"(c[0]), "+f"(c[1]), "+f"(c[2]), "+f"(c[3])
        : "r"(a0), "r"(a1), "r"(a2), "r"(a3), "r"(b0), "r"(b1));
}
__device__ __forceinline__ u32 smem_u32(const void* p) {
    u32 a;
    asm("{ .reg .u64 t; cvta.to.shared.u64 t, %1; cvt.u32.u64 %0, t; }"
        : "=r"(a) : "l"(p));
    return a;
}
#define LDSM_X4(r0, r1, r2, r3, addr) \
    asm volatile("ldmatrix.sync.aligned.m8n8.x4.shared.b16 {%0,%1,%2,%3}, [%4];" \
        : "=r"(r0), "=r"(r1), "=r"(r2), "=r"(r3) : "r"(addr))
#define CP_ASYNC16(dst, src) \
    asm volatile("cp.async.cg.shared.global [%0], [%1], 16;" \
                 :: "r"(dst), "l"(src) : "memory")
#define CP_COMMIT() asm volatile("cp.async.commit_group;" ::: "memory")
#define CP_WAIT0()  asm volatile("cp.async.wait_group 0;" ::: "memory")

// ===========================================================================
// Mask prep (dtype sniff: uint8 / int32 / float32) — proven
// ===========================================================================
__global__ void mask_prep(const unsigned char* __restrict__ m)
{
    __shared__ int s_cnt[2];
    const int tid = threadIdx.x;
    if (tid < 2) s_cnt[tid] = 0;
    __syncthreads();
    int c1 = 0, c0 = 0;
    for (int i = tid; i < (Bn*Sn)/4; i += blockDim.x) {
        uchar4 v = ((const uchar4*)m)[i];
        if (v.y) c1++;
        if (v.x) c0++;
    }
    atomicAdd(&s_cnt[0], c1);
    atomicAdd(&s_cnt[1], c0);
    __syncthreads();
    const int mode = (s_cnt[0] > 0) ? 0 : ((s_cnt[1] > 0) ? 1 : 2);
    for (int i = tid; i < Bn*Sn; i += blockDim.x) {
        float f;
        if (mode == 0)      f = m[i] ? 1.f : 0.f;
        else if (mode == 1) f = (((const int*)m)[i] != 0) ? 1.f : 0.f;
        else                f = (((const float*)m)[i] != 0.f) ? 1.f : 0.f;
        g_maskf[i] = f;
    }
}

// ===========================================================================
// KV prep (unchanged, proven)
// ===========================================================================
__global__ __launch_bounds__(256)
void kv_prep()
{
    __shared__ float vt[32][65];
    const int tid = threadIdx.x;
    const int bh = blockIdx.z * Hn + blockIdx.y;
    const int s0 = blockIdx.x * 32;
    const float* Ks = g_K + ((size_t)bh*Sn + s0)*Dn;
    const float* Vs = g_V + ((size_t)bh*Sn + s0)*Dn;

    #pragma unroll
    for (int i = 0; i < 2; i++) {
        int f4 = tid + (i << 8);
        int row = f4 >> 4, dim = (f4 & 15) * 4;
        float4 v = *(const float4*)&Ks[row*Dn + dim];
        u32 h0,l0,h1,l1,h2,l2,h3,l3;
        bsplit(v.x,h0,l0); bsplit(v.y,h1,l1); bsplit(v.z,h2,l2); bsplit(v.w,h3,l3);
        size_t o = ((size_t)bh*Sn + s0 + row)*Dn + dim;
        *(uint2*)&g_Kbh[o] = make_uint2(h0|(h1<<16), h2|(h3<<16));
        *(uint2*)&g_Kbl[o] = make_uint2(l0|(l1<<16), l2|(l3<<16));
        float4 w = *(const float4*)&Vs[row*Dn + dim];
        vt[row][dim] = w.x; vt[row][dim+1] = w.y;
        vt[row][dim+2] = w.z; vt[row][dim+3] = w.w;
    }
    __syncthreads();
    #pragma unroll
    for (int i = 0; i < 4; i++) {
        int u = tid + (i << 8);
        int d = u >> 4, j = u & 15;
        float v0 = vt[2*j][d], v1 = vt[2*j+1][d];
        u32 h0,l0,h1,l1;
        bsplit(v0,h0,l0); bsplit(v1,h1,l1);
        size_t o = ((size_t)bh*Dn + d)*Sn + s0 + 2*j;
        *(u32*)&g_Vth[o] = h0 | (h1<<16);
        *(u32*)&g_Vtl[o] = l0 | (l1<<16);
    }
}

// ===========================================================================
// Tensor-core GEMM with ldmatrix fragment loads.
// GK_STRIDE bumped 36 -> 40 bf16 (80B rows: 16B-aligned for ldmatrix,
// 20-word stride -> conflict-free 8-row reads).
// ===========================================================================
#define GK_STRIDE 40
#define GROWB 80                      // row bytes
#define PLANE (128*GROWB)             // 10240 B
#define AHI 0
#define ALO PLANE
#define BHI (2*PLANE)
#define BLO (3*PLANE)
#define STG (4*PLANE)                 // 40960 B
#define GEMM_SMEM (2*STG)             // 81920 B

template<int MODE>
__global__ __launch_bounds__(256, 1)
void gemm_mma(const float* __restrict__ A,
              const float* __restrict__ W0, const float* __restrict__ bias0,
              const float* __restrict__ W1, const float* __restrict__ bias1,
              const float* __restrict__ W2, const float* __restrict__ bias2,
              float* __restrict__ outp)
{
    extern __shared__ char smem[];
    const u32 sbG = smem_u32(smem);
    const int tid = threadIdx.x;
    const int wid = tid >> 5;
    const int lid = tid & 31;
    const int wm  = wid & 3;
    const int wn  = wid >> 2;
    const int m0 = blockIdx.y * 128;
    const int n0 = blockIdx.x * 128;

    const float* W    = W0;
    const float* bias = bias0;
    float* outq = nullptr;
    if (MODE == 1) {
        int z = blockIdx.z;
        W    = (z==0) ? W0    : ((z==1) ? W1    : W2);
        bias = (z==0) ? bias0 : ((z==1) ? bias1 : bias2);
        outq = (z==0) ? g_Q   : ((z==1) ? g_K   : g_V);
    }
    const float* Ap = (MODE == 1) ? A : g_A;

    float c[2][8][4];
    #pragma unroll
    for (int mt = 0; mt < 2; mt++)
        #pragma unroll
        for (int nt = 0; nt < 8; nt++)
            #pragma unroll
            for (int r = 0; r < 4; r++) c[mt][nt][r] = 0.f;

    // ldmatrix lane-address components
    const u32 nOff8  = ((lid >> 4) & 1) * 8 + (lid & 7);
    const u32 kOff16 = ((lid >> 3) & 1) * 16;
    const u32 aRow0  = (u32)(wm*32 + (lid & 15)) * GROWB + ((lid >> 4) << 4);
    const u32 qrow = lid >> 2;

    float4 va[4], vb[4];
    #pragma unroll
    for (int i = 0; i < 4; i++) {
        int f4 = tid + i*256;
        int row = f4 >> 3, c4 = f4 & 7;
        va[i] = *(const float4*)&Ap[(size_t)(m0 + row)*En + c4*4];
        vb[i] = *(const float4*)&W [(size_t)(n0 + row)*En + c4*4];
    }

    const int NKT = En / 32;
    for (int kt = 0; kt < NKT; kt++) {
        {
            char* stg = smem + (kt & 1) * STG;
            #pragma unroll
            for (int i = 0; i < 4; i++) {
                int f4 = tid + i*256;
                int row = f4 >> 3, c4 = f4 & 7;
                int off = row*GROWB + c4*8;
                u32 h0,l0,h1,l1,h2,l2,h3,l3;
                bsplit(va[i].x, h0, l0); bsplit(va[i].y, h1, l1);
                bsplit(va[i].z, h2, l2); bsplit(va[i].w, h3, l3);
                *(uint2*)(stg + AHI + off) = make_uint2(h0|(h1<<16), h2|(h3<<16));
                *(uint2*)(stg + ALO + off) = make_uint2(l0|(l1<<16), l2|(l3<<16));
                bsplit(vb[i].x, h0, l0); bsplit(vb[i].y, h1, l1);
                bsplit(vb[i].z, h2, l2); bsplit(vb[i].w, h3, l3);
                *(uint2*)(stg + BHI + off) = make_uint2(h0|(h1<<16), h2|(h3<<16));
                *(uint2*)(stg + BLO + off) = make_uint2(l0|(l1<<16), l2|(l3<<16));
            }
        }
        __syncthreads();

        if (kt + 1 < NKT) {
            const int k0 = (kt + 1) * 32;
            #pragma unroll
            for (int i = 0; i < 4; i++) {
                int f4 = tid + i*256;
                int row = f4 >> 3, c4 = f4 & 7;
                va[i] = *(const float4*)&Ap[(size_t)(m0 + row)*En + k0 + c4*4];
                vb[i] = *(const float4*)&W [(size_t)(n0 + row)*En + k0 + c4*4];
            }
        }

        const u32 stgu = sbG + (kt & 1) * STG;
        #pragma unroll
        for (int ks = 0; ks < 2; ks++) {
            const int kb = ks * 32;
            u32 ah[2][4], al[2][4], bh[8][2], bl[8][2];
            #pragma unroll
            for (int mt = 0; mt < 2; mt++) {
                u32 adr = stgu + AHI + aRow0 + (u32)(mt*16)*GROWB + kb;
                LDSM_X4(ah[mt][0], ah[mt][1], ah[mt][2], ah[mt][3], adr);
                LDSM_X4(al[mt][0], al[mt][1], al[mt][2], al[mt][3], adr + (ALO - AHI));
            }
            #pragma unroll
            for (int p = 0; p < 4; p++) {
                u32 adr = stgu + BHI
                        + (u32)(wn*64 + p*16 + nOff8)*GROWB + kOff16 + kb;
                LDSM_X4(bh[2*p][0], bh[2*p][1], bh[2*p+1][0], bh[2*p+1][1], adr);
                LDSM_X4(bl[2*p][0], bl[2*p][1], bl[2*p+1][0], bl[2*p+1][1],
                        adr + (BLO - BHI));
            }
            #pragma unroll
            for (int mt = 0; mt < 2; mt++)
                #pragma unroll
                for (int nt = 0; nt < 8; nt++) {
                    mma_bf16(c[mt][nt], ah[mt][0], ah[mt][1], ah[mt][2], ah[mt][3],
                             bh[nt][0], bh[nt][1]);
                    mma_bf16(c[mt][nt], ah[mt][0], ah[mt][1], ah[mt][2], ah[mt][3],
                             bl[nt][0], bl[nt][1]);
                    mma_bf16(c[mt][nt], al[mt][0], al[mt][1], al[mt][2], al[mt][3],
                             bh[nt][0], bh[nt][1]);
                }
        }
        if (kt + 1 < NKT) __syncthreads();
    }

    #pragma unroll
    for (int mt = 0; mt < 2; mt++) {
        #pragma unroll
        for (int nt = 0; nt < 8; nt++) {
            int row = m0 + wm*32 + mt*16 + qrow;
            int col = n0 + wn*64 + nt*8 + (lid & 3)*2;
            float b0 = bias[col], b1 = bias[col + 1];
            float2 lo = make_float2(c[mt][nt][0] + b0, c[mt][nt][1] + b1);
            float2 hi = make_float2(c[mt][nt][2] + b0, c[mt][nt][3] + b1);
            if (MODE == 1) {
                int bb = row >> 11;
                int h  = col >> 6;
                int d  = col & 63;
                size_t base = ((size_t)(bb*Hn + h)*Sn) * Dn + d;
                *(float2*)&outq[base + (size_t)(row & (Sn-1))*Dn]       = lo;
                *(float2*)&outq[base + (size_t)((row & (Sn-1)) + 8)*Dn] = hi;
            } else {
                *(float2*)&outp[(size_t)row*En + col]       = lo;
                *(float2*)&outp[(size_t)(row + 8)*En + col] = hi;
            }
        }
    }
}

// ===========================================================================
// Tensor-core flash attention with ldmatrix fragment loads.
// Layout identical to R10 (strides 144/272B are 16B-aligned, conflict-free).
// ===========================================================================
#define SQB 144
#define SVB 272
#define OFF_QL   18432
#define OFF_STAGE 36864
#define AKL   18432
#define AVH   36864
#define AVL   54272
#define STAGE_SZ 71680
#define OFF_MS (OFF_STAGE + 2*STAGE_SZ)
#define ATT_SMEM (OFF_MS + 1024)

__global__ __launch_bounds__(256, 1)
void attn_tc()
{
    extern __shared__ char sm[];
    const u32 sb = smem_u32(sm);
    const int tid = threadIdx.x;
    const int wid = tid >> 5, lid = tid & 31;
    const int qr = lid >> 2, qc = lid & 3;
    const int qt = blockIdx.x, h = blockIdx.y, b = blockIdx.z;
    const int bh = b*Hn + h;

    const float* Qg = g_Q + ((size_t)bh*Sn + qt*128)*Dn;
    const float* mk = g_maskf + b*Sn;
    const unsigned short* Khg = g_Kbh + (size_t)bh*Sn*Dn;
    const unsigned short* Klg = g_Kbl + (size_t)bh*Sn*Dn;
    const unsigned short* Vhg = g_Vth + (size_t)bh*Dn*Sn;
    const unsigned short* Vlg = g_Vtl + (size_t)bh*Dn*Sn;
    float* mS = (float*)(sm + OFF_MS);

    // ---- Q load + 0.125 scale + split into smem (persistent) ----
    #pragma unroll
    for (int i = 0; i < 8; i++) {
        int f4 = tid + (i << 8);
        int row = f4 >> 4, dim = (f4 & 15) << 2;
        float4 v = *(const float4*)&Qg[row*Dn + dim];
        v.x *= 0.125f; v.y *= 0.125f; v.z *= 0.125f; v.w *= 0.125f;
        u32 h0,l0,h1,l1,h2,l2,h3,l3;
        bsplit(v.x,h0,l0); bsplit(v.y,h1,l1); bsplit(v.z,h2,l2); bsplit(v.w,h3,l3);
        *(uint2*)(sm + row*SQB + dim*2)          = make_uint2(h0|(h1<<16), h2|(h3<<16));
        *(uint2*)(sm + OFF_QL + row*SQB + dim*2) = make_uint2(l0|(l1<<16), l2|(l3<<16));
    }

    auto issue = [&](int kt, int st) {
        const u32 stg = sb + OFF_STAGE + st*STAGE_SZ;
        #pragma unroll
        for (int i = 0; i < 16; i++) {
            int c = tid + (i << 8);
            if (c < 2048) {
                int pl = c >> 10, row = (c >> 3) & 127, col = c & 7;
                const unsigned short* src = (pl ? Klg : Khg)
                    + (size_t)(kt*128 + row)*Dn + col*8;
                CP_ASYNC16(stg + pl*AKL + row*SQB + col*16, src);
            } else {
                int c2 = c - 2048;
                int pl = c2 >> 10, d = (c2 >> 4) & 63, col = c2 & 15;
                const unsigned short* src = (pl ? Vlg : Vhg)
                    + (size_t)d*Sn + kt*128 + col*8;
                CP_ASYNC16(stg + AVH + pl*(AVL-AVH) + d*SVB + col*16, src);
            }
        }
        if (tid < 128) mS[st*128 + tid] = mk[kt*128 + tid];
        CP_COMMIT();
    };

    float m0 = -INFINITY, m1 = -INFINITY, l0 = 0.f, l1 = 0.f;
    float acc[8][4];
    #pragma unroll
    for (int nt = 0; nt < 8; nt++)
        #pragma unroll
        for (int r = 0; r < 4; r++) acc[nt][r] = 0.f;

    issue(0, 0);

    // ldmatrix lane-address components
    const u32 nOff8  = ((lid >> 4) & 1) * 8 + (lid & 7);
    const u32 kOff16 = ((lid >> 3) & 1) * 16;
    const u32 qAhi = sb + (u32)(wid*16 + (lid & 15))*SQB + ((lid >> 4) << 4);

    for (int kt = 0; kt < Sn/128; kt++) {
        const int st = kt & 1;
        CP_WAIT0();
        __syncthreads();
        if (kt + 1 < Sn/128) issue(kt + 1, 1 - st);

        const u32 KHu = sb + OFF_STAGE + st*STAGE_SZ;
        const u32 KLu = KHu + AKL;
        const u32 VHu = KHu + AVH;
        const u32 VLu = KHu + AVL;

        // ---- QK^T: scores [16 x 128] per warp ----
        float sc[16][4];
        #pragma unroll
        for (int nt = 0; nt < 16; nt++)
            #pragma unroll
            for (int r = 0; r < 4; r++) sc[nt][r] = 0.f;

        #pragma unroll
        for (int ks = 0; ks < 4; ks++) {
            u32 ah[4], al[4];
            LDSM_X4(ah[0], ah[1], ah[2], ah[3], qAhi + ks*32);
            LDSM_X4(al[0], al[1], al[2], al[3], qAhi + OFF_QL + ks*32);
            #pragma unroll
            for (int p = 0; p < 8; p++) {
                u32 badr = (u32)(p*16 + nOff8)*SQB + kOff16 + ks*32;
                u32 bh0, bh1, bh2, bh3, bl0, bl1, bl2, bl3;
                LDSM_X4(bh0, bh1, bh2, bh3, KHu + badr);
                LDSM_X4(bl0, bl1, bl2, bl3, KLu + badr);
                mma_bf16(sc[2*p],   ah[0], ah[1], ah[2], ah[3], bh0, bh1);
                mma_bf16(sc[2*p],   ah[0], ah[1], ah[2], ah[3], bl0, bl1);
                mma_bf16(sc[2*p],   al[0], al[1], al[2], al[3], bh0, bh1);
                mma_bf16(sc[2*p+1], ah[0], ah[1], ah[2], ah[3], bh2, bh3);
                mma_bf16(sc[2*p+1], ah[0], ah[1], ah[2], ah[3], bl2, bl3);
                mma_bf16(sc[2*p+1], al[0], al[1], al[2], al[3], bh2, bh3);
            }
        }

        // ---- mask ----
        const float* msk = mS + st*128;
        #pragma unroll
        for (int nt = 0; nt < 16; nt++) {
            int c0 = nt*8 + qc*2;
            if (msk[c0]   != 0.f) { sc[nt][0] = -1e9f; sc[nt][2] = -1e9f; }
            if (msk[c0+1] != 0.f) { sc[nt][1] = -1e9f; sc[nt][3] = -1e9f; }
        }

        // ---- online softmax ----
        float mx0 = -INFINITY, mx1 = -INFINITY;
        #pragma unroll
        for (int nt = 0; nt < 16; nt++) {
            mx0 = fmaxf(mx0, fmaxf(sc[nt][0], sc[nt][1]));
            mx1 = fmaxf(mx1, fmaxf(sc[nt][2], sc[nt][3]));
        }
        mx0 = fmaxf(mx0, __shfl_xor_sync(0xffffffffu, mx0, 1));
        mx0 = fmaxf(mx0, __shfl_xor_sync(0xffffffffu, mx0, 2));
        mx1 = fmaxf(mx1, __shfl_xor_sync(0xffffffffu, mx1, 1));
        mx1 = fmaxf(mx1, __shfl_xor_sync(0xffffffffu, mx1, 2));
        float mn0 = fmaxf(m0, mx0), mn1 = fmaxf(m1, mx1);
        float fs0 = __expf(m0 - mn0), fs1 = __expf(m1 - mn1);
        m0 = mn0; m1 = mn1;

        float ps0 = 0.f, ps1 = 0.f;
        #pragma unroll
        for (int nt = 0; nt < 16; nt++) {
            float p0 = __expf(sc[nt][0] - mn0);
            float p1 = __expf(sc[nt][1] - mn0);
            float p2 = __expf(sc[nt][2] - mn1);
            float p3 = __expf(sc[nt][3] - mn1);
            ps0 += p0 + p1; ps1 += p2 + p3;
            sc[nt][0] = p0; sc[nt][1] = p1; sc[nt][2] = p2; sc[nt][3] = p3;
        }
        ps0 += __shfl_xor_sync(0xffffffffu, ps0, 1);
        ps0 += __shfl_xor_sync(0xffffffffu, ps0, 2);
        ps1 += __shfl_xor_sync(0xffffffffu, ps1, 1);
        ps1 += __shfl_xor_sync(0xffffffffu, ps1, 2);
        l0 = l0*fs0 + ps0;
        l1 = l1*fs1 + ps1;

        #pragma unroll
        for (int nt = 0; nt < 8; nt++) {
            acc[nt][0] *= fs0; acc[nt][1] *= fs0;
            acc[nt][2] *= fs1; acc[nt][3] *= fs1;
        }

        // ---- PV ----
        #pragma unroll
        for (int hf = 0; hf < 2; hf++) {
            u32 pah[4][4], pal[4][4];
            #pragma unroll
            for (int ksl = 0; ksl < 4; ksl++) {
                int kp = hf*4 + ksl;
                psplit2(sc[2*kp][0],   sc[2*kp][1],   pah[ksl][0], pal[ksl][0]);
                psplit2(sc[2*kp][2],   sc[2*kp][3],   pah[ksl][1], pal[ksl][1]);
                psplit2(sc[2*kp+1][0], sc[2*kp+1][1], pah[ksl][2], pal[ksl][2]);
                psplit2(sc[2*kp+1][2], sc[2*kp+1][3], pah[ksl][3], pal[ksl][3]);
            }
            #pragma unroll
            for (int ksl = 0; ksl < 4; ksl++) {
                int ks = hf*4 + ksl;
                #pragma unroll
                for (int p = 0; p < 4; p++) {
                    u32 vadr = (u32)(p*16 + nOff8)*SVB + kOff16 + ks*32;
                    u32 vh0, vh1, vh2, vh3, vl0, vl1, vl2, vl3;
                    LDSM_X4(vh0, vh1, vh2, vh3, VHu + vadr);
                    LDSM_X4(vl0, vl1, vl2, vl3, VLu + vadr);
                    mma_bf16(acc[2*p], pah[ksl][0], pah[ksl][1], pah[ksl][2],
                             pah[ksl][3], vh0, vh1);
                    mma_bf16(acc[2*p], pal[ksl][0], pal[ksl][1], pal[ksl][2],
                             pal[ksl][3], vh0, vh1);
                    mma_bf16(acc[2*p], pah[ksl][0], pah[ksl][1], pah[ksl][2],
                             pah[ksl][3], vl0, vl1);
                    mma_bf16(acc[2*p+1], pah[ksl][0], pah[ksl][1], pah[ksl][2],
                             pah[ksl][3], vh2, vh3);
                    mma_bf16(acc[2*p+1], pal[ksl][0], pal[ksl][1], pal[ksl][2],
                             pal[ksl][3], vh2, vh3);
                    mma_bf16(acc[2*p+1], pah[ksl][0], pah[ksl][1], pah[ksl][2],
                             pah[ksl][3], vl2, vl3);
                }
            }
        }
    }

    // ---- epilogue ----
    float inv0 = 1.f / l0, inv1 = 1.f / l1;
    int row0 = qt*128 + wid*16 + qr;
    #pragma unroll
    for (int nt = 0; nt < 8; nt++) {
        int d = h*64 + nt*8 + qc*2;
        *(float2*)&g_A[((size_t)(b*Sn + row0))*En + d] =
            make_float2(acc[nt][0]*inv0, acc[nt][1]*inv0);
        *(float2*)&g_A[((size_t)(b*Sn + row0 + 8))*En + d] =
            make_float2(acc[nt][2]*inv1, acc[nt][3]*inv1);
    }
}

// ---------------------------------------------------------------------------
extern "C" void kernel_launch(void* const* d_in, const int* in_sizes, int n_in,
                              void* d_out, int out_size)
{
    const float* x  = (const float*)d_in[0];
    const unsigned char* mask = (const unsigned char*)d_in[1];
    const float* Wq = (const float*)d_in[2];
    const float* bq = (const float*)d_in[3];
    const float* Wk = (const float*)d_in[4];
    const float* bk = (const float*)d_in[5];
    const float* Wv = (const float*)d_in[6];
    const float* bv = (const float*)d_in[7];
    const float* Wo = (const float*)d_in[8];
    const float* bo = (const float*)d_in[9];
    float* out = (float*)d_out;

    cudaFuncSetAttribute(gemm_mma<1>,
                         cudaFuncAttributeMaxDynamicSharedMemorySize, GEMM_SMEM);
    cudaFuncSetAttribute(gemm_mma<0>,
                         cudaFuncAttributeMaxDynamicSharedMemorySize, GEMM_SMEM);
    cudaFuncSetAttribute(attn_tc,
                         cudaFuncAttributeMaxDynamicSharedMemorySize, ATT_SMEM);

    mask_prep<<<1, 256>>>(mask);

    gemm_mma<1><<<dim3(En/128, Mn/128, 3), 256, GEMM_SMEM>>>(
        x, Wq, bq, Wk, bk, Wv, bv, nullptr);

    kv_prep<<<dim3(Sn/32, Hn, Bn), 256>>>();

    attn_tc<<<dim3(Sn/128, Hn, Bn), 256, ATT_SMEM>>>();

    gemm_mma<0><<<dim3(En/128, Mn/128, 1), 256, GEMM_SMEM>>>(
        nullptr, Wo, bo, nullptr, nullptr, nullptr, nullptr, out);
}

// round 12
// speedup vs baseline: 3.2481x; 1.0444x over previous
#include <cuda_runtime.h>
#include <math.h>
#include <cstdint>

typedef uint32_t u32;

// Problem constants
#define Bn 2
#define Sn 2048
#define En 1024
#define Hn 16
#define Dn 64
#define Mn (Bn*Sn)   // 4096 rows

// Scratch (static __device__ arrays: allocation-guard safe)
__device__ float g_Q[Bn*Hn*Sn*Dn];   // [B,H,S,D]
__device__ float g_K[Bn*Hn*Sn*Dn];
__device__ float g_V[Bn*Hn*Sn*Dn];
__device__ float g_A[Mn*En];         // attention output, [B,S,E]
__device__ float g_maskf[Bn*Sn];     // normalized mask: 1.0 = masked out
// bf16 split copies for tensor-core attention
__device__ unsigned short g_Kbh[Bn*Hn*Sn*Dn];  // [B,H,S,D] hi
__device__ unsigned short g_Kbl[Bn*Hn*Sn*Dn];  // [B,H,S,D] lo
__device__ unsigned short g_Vth[Bn*Hn*Dn*Sn];  // [B,H,D,S] hi (transposed)
__device__ unsigned short g_Vtl[Bn*Hn*Dn*Sn];  // [B,H,D,S] lo

// ===========================================================================
// helpers
// ===========================================================================
__device__ __forceinline__ void bsplit(float x, u32& h, u32& l) {
    u32 u = __float_as_uint(x);
    h = u >> 16;
    float lo = x - __uint_as_float(u & 0xFFFF0000u);
    l = __float_as_uint(lo) >> 16;
}
__device__ __forceinline__ void psplit2(float x, float y, u32& hp, u32& lp) {
    u32 ux = __float_as_uint(x), uy = __float_as_uint(y);
    float xl = x - __uint_as_float(ux & 0xFFFF0000u);
    float yl = y - __uint_as_float(uy & 0xFFFF0000u);
    hp = (ux >> 16) | (uy & 0xFFFF0000u);
    lp = (__float_as_uint(xl) >> 16) | (__float_as_uint(yl) & 0xFFFF0000u);
}
__device__ __forceinline__ void mma_bf16(float* c, u32 a0, u32 a1,
                                         u32 a2, u32 a3, u32 b0, u32 b1) {
    asm volatile(
        "mma.sync.aligned.m16n8k16.row.col.f32.bf16.bf16.f32 "
        "{%0,%1,%2,%3}, {%4,%5,%6,%7}, {%8,%9}, {%0,%1,%2,%3};"
        : "+f"(c[0]), "+f"(c[1]), "+f"(c[2]), "+f"(c[3])
        : "r"(a0), "r"(a1), "r"(a2), "r"(a3), "r"(b0), "r"(b1));
}
__device__ __forceinline__ u32 smem_u32(const void* p) {
    u32 a;
    asm("{ .reg .u64 t; cvta.to.shared.u64 t, %1; cvt.u32.u64 %0, t; }"
        : "=r"(a) : "l"(p));
    return a;
}
#define LDSM_X4(r0, r1, r2, r3, addr) \
    asm volatile("ldmatrix.sync.aligned.m8n8.x4.shared.b16 {%0,%1,%2,%3}, [%4];" \
        : "=r"(r0), "=r"(r1), "=r"(r2), "=r"(r3) : "r"(addr))
#define CP_ASYNC16(dst, src) \
    asm volatile("cp.async.cg.shared.global [%0], [%1], 16;" \
                 :: "r"(dst), "l"(src) : "memory")
#define CP_COMMIT() asm volatile("cp.async.commit_group;" ::: "memory")
#define CP_WAIT0()  asm volatile("cp.async.wait_group 0;" ::: "memory")

// ===========================================================================
// Mask prep (dtype sniff) — proven
// ===========================================================================
__global__ void mask_prep(const unsigned char* __restrict__ m)
{
    __shared__ int s_cnt[2];
    const int tid = threadIdx.x;
    if (tid < 2) s_cnt[tid] = 0;
    __syncthreads();
    int c1 = 0, c0 = 0;
    for (int i = tid; i < (Bn*Sn)/4; i += blockDim.x) {
        uchar4 v = ((const uchar4*)m)[i];
        if (v.y) c1++;
        if (v.x) c0++;
    }
    atomicAdd(&s_cnt[0], c1);
    atomicAdd(&s_cnt[1], c0);
    __syncthreads();
    const int mode = (s_cnt[0] > 0) ? 0 : ((s_cnt[1] > 0) ? 1 : 2);
    for (int i = tid; i < Bn*Sn; i += blockDim.x) {
        float f;
        if (mode == 0)      f = m[i] ? 1.f : 0.f;
        else if (mode == 1) f = (((const int*)m)[i] != 0) ? 1.f : 0.f;
        else                f = (((const float*)m)[i] != 0.f) ? 1.f : 0.f;
        g_maskf[i] = f;
    }
}

// ===========================================================================
// KV prep (unchanged, proven)
// ===========================================================================
__global__ __launch_bounds__(256)
void kv_prep()
{
    __shared__ float vt[32][65];
    const int tid = threadIdx.x;
    const int bh = blockIdx.z * Hn + blockIdx.y;
    const int s0 = blockIdx.x * 32;
    const float* Ks = g_K + ((size_t)bh*Sn + s0)*Dn;
    const float* Vs = g_V + ((size_t)bh*Sn + s0)*Dn;

    #pragma unroll
    for (int i = 0; i < 2; i++) {
        int f4 = tid + (i << 8);
        int row = f4 >> 4, dim = (f4 & 15) * 4;
        float4 v = *(const float4*)&Ks[row*Dn + dim];
        u32 h0,l0,h1,l1,h2,l2,h3,l3;
        bsplit(v.x,h0,l0); bsplit(v.y,h1,l1); bsplit(v.z,h2,l2); bsplit(v.w,h3,l3);
        size_t o = ((size_t)bh*Sn + s0 + row)*Dn + dim;
        *(uint2*)&g_Kbh[o] = make_uint2(h0|(h1<<16), h2|(h3<<16));
        *(uint2*)&g_Kbl[o] = make_uint2(l0|(l1<<16), l2|(l3<<16));
        float4 w = *(const float4*)&Vs[row*Dn + dim];
        vt[row][dim] = w.x; vt[row][dim+1] = w.y;
        vt[row][dim+2] = w.z; vt[row][dim+3] = w.w;
    }
    __syncthreads();
    #pragma unroll
    for (int i = 0; i < 4; i++) {
        int u = tid + (i << 8);
        int d = u >> 4, j = u & 15;
        float v0 = vt[2*j][d], v1 = vt[2*j+1][d];
        u32 h0,l0,h1,l1;
        bsplit(v0,h0,l0); bsplit(v1,h1,l1);
        size_t o = ((size_t)bh*Dn + d)*Sn + s0 + 2*j;
        *(u32*)&g_Vth[o] = h0 | (h1<<16);
        *(u32*)&g_Vtl[o] = l0 | (l1<<16);
    }
}

// ===========================================================================
// Tensor-core GEMM with ldmatrix (unchanged from R11, passing)
// ===========================================================================
#define GK_STRIDE 40
#define GROWB 80
#define PLANE (128*GROWB)
#define AHI 0
#define ALO PLANE
#define BHI (2*PLANE)
#define BLO (3*PLANE)
#define STG (4*PLANE)
#define GEMM_SMEM (2*STG)

template<int MODE>
__global__ __launch_bounds__(256, 1)
void gemm_mma(const float* __restrict__ A,
              const float* __restrict__ W0, const float* __restrict__ bias0,
              const float* __restrict__ W1, const float* __restrict__ bias1,
              const float* __restrict__ W2, const float* __restrict__ bias2,
              float* __restrict__ outp)
{
    extern __shared__ char smem[];
    const u32 sbG = smem_u32(smem);
    const int tid = threadIdx.x;
    const int wid = tid >> 5;
    const int lid = tid & 31;
    const int wm  = wid & 3;
    const int wn  = wid >> 2;
    const int m0 = blockIdx.y * 128;
    const int n0 = blockIdx.x * 128;

    const float* W    = W0;
    const float* bias = bias0;
    float* outq = nullptr;
    if (MODE == 1) {
        int z = blockIdx.z;
        W    = (z==0) ? W0    : ((z==1) ? W1    : W2);
        bias = (z==0) ? bias0 : ((z==1) ? bias1 : bias2);
        outq = (z==0) ? g_Q   : ((z==1) ? g_K   : g_V);
    }
    const float* Ap = (MODE == 1) ? A : g_A;

    float c[2][8][4];
    #pragma unroll
    for (int mt = 0; mt < 2; mt++)
        #pragma unroll
        for (int nt = 0; nt < 8; nt++)
            #pragma unroll
            for (int r = 0; r < 4; r++) c[mt][nt][r] = 0.f;

    const u32 nOff8  = ((lid >> 4) & 1) * 8 + (lid & 7);
    const u32 kOff16 = ((lid >> 3) & 1) * 16;
    const u32 aRow0  = (u32)(wm*32 + (lid & 15)) * GROWB + ((lid >> 4) << 4);
    const u32 qrow = lid >> 2;

    float4 va[4], vb[4];
    #pragma unroll
    for (int i = 0; i < 4; i++) {
        int f4 = tid + i*256;
        int row = f4 >> 3, c4 = f4 & 7;
        va[i] = *(const float4*)&Ap[(size_t)(m0 + row)*En + c4*4];
        vb[i] = *(const float4*)&W [(size_t)(n0 + row)*En + c4*4];
    }

    const int NKT = En / 32;
    for (int kt = 0; kt < NKT; kt++) {
        {
            char* stg = smem + (kt & 1) * STG;
            #pragma unroll
            for (int i = 0; i < 4; i++) {
                int f4 = tid + i*256;
                int row = f4 >> 3, c4 = f4 & 7;
                int off = row*GROWB + c4*8;
                u32 h0,l0,h1,l1,h2,l2,h3,l3;
                bsplit(va[i].x, h0, l0); bsplit(va[i].y, h1, l1);
                bsplit(va[i].z, h2, l2); bsplit(va[i].w, h3, l3);
                *(uint2*)(stg + AHI + off) = make_uint2(h0|(h1<<16), h2|(h3<<16));
                *(uint2*)(stg + ALO + off) = make_uint2(l0|(l1<<16), l2|(l3<<16));
                bsplit(vb[i].x, h0, l0); bsplit(vb[i].y, h1, l1);
                bsplit(vb[i].z, h2, l2); bsplit(vb[i].w, h3, l3);
                *(uint2*)(stg + BHI + off) = make_uint2(h0|(h1<<16), h2|(h3<<16));
                *(uint2*)(stg + BLO + off) = make_uint2(l0|(l1<<16), l2|(l3<<16));
            }
        }
        __syncthreads();

        if (kt + 1 < NKT) {
            const int k0 = (kt + 1) * 32;
            #pragma unroll
            for (int i = 0; i < 4; i++) {
                int f4 = tid + i*256;
                int row = f4 >> 3, c4 = f4 & 7;
                va[i] = *(const float4*)&Ap[(size_t)(m0 + row)*En + k0 + c4*4];
                vb[i] = *(const float4*)&W [(size_t)(n0 + row)*En + k0 + c4*4];
            }
        }

        const u32 stgu = sbG + (kt & 1) * STG;
        #pragma unroll
        for (int ks = 0; ks < 2; ks++) {
            const int kb = ks * 32;
            u32 ah[2][4], al[2][4], bh[8][2], bl[8][2];
            #pragma unroll
            for (int mt = 0; mt < 2; mt++) {
                u32 adr = stgu + AHI + aRow0 + (u32)(mt*16)*GROWB + kb;
                LDSM_X4(ah[mt][0], ah[mt][1], ah[mt][2], ah[mt][3], adr);
                LDSM_X4(al[mt][0], al[mt][1], al[mt][2], al[mt][3], adr + (ALO - AHI));
            }
            #pragma unroll
            for (int p = 0; p < 4; p++) {
                u32 adr = stgu + BHI
                        + (u32)(wn*64 + p*16 + nOff8)*GROWB + kOff16 + kb;
                LDSM_X4(bh[2*p][0], bh[2*p][1], bh[2*p+1][0], bh[2*p+1][1], adr);
                LDSM_X4(bl[2*p][0], bl[2*p][1], bl[2*p+1][0], bl[2*p+1][1],
                        adr + (BLO - BHI));
            }
            #pragma unroll
            for (int mt = 0; mt < 2; mt++)
                #pragma unroll
                for (int nt = 0; nt < 8; nt++) {
                    mma_bf16(c[mt][nt], ah[mt][0], ah[mt][1], ah[mt][2], ah[mt][3],
                             bh[nt][0], bh[nt][1]);
                    mma_bf16(c[mt][nt], ah[mt][0], ah[mt][1], ah[mt][2], ah[mt][3],
                             bl[nt][0], bl[nt][1]);
                    mma_bf16(c[mt][nt], al[mt][0], al[mt][1], al[mt][2], al[mt][3],
                             bh[nt][0], bh[nt][1]);
                }
        }
        if (kt + 1 < NKT) __syncthreads();
    }

    #pragma unroll
    for (int mt = 0; mt < 2; mt++) {
        #pragma unroll
        for (int nt = 0; nt < 8; nt++) {
            int row = m0 + wm*32 + mt*16 + qrow;
            int col = n0 + wn*64 + nt*8 + (lid & 3)*2;
            float b0 = bias[col], b1 = bias[col + 1];
            float2 lo = make_float2(c[mt][nt][0] + b0, c[mt][nt][1] + b1);
            float2 hi = make_float2(c[mt][nt][2] + b0, c[mt][nt][3] + b1);
            if (MODE == 1) {
                int bb = row >> 11;
                int h  = col >> 6;
                int d  = col & 63;
                size_t base = ((size_t)(bb*Hn + h)*Sn) * Dn + d;
                *(float2*)&outq[base + (size_t)(row & (Sn-1))*Dn]       = lo;
                *(float2*)&outq[base + (size_t)((row & (Sn-1)) + 8)*Dn] = hi;
            } else {
                *(float2*)&outp[(size_t)row*En + col]       = lo;
                *(float2*)&outp[(size_t)(row + 8)*En + col] = hi;
            }
        }
    }
}

// ===========================================================================
// Tensor-core flash attention, 2-CTA-per-SM version.
// CTA = 128 threads (4 warps), q-tile 64, key-tile 64, cp.async double buffer.
// Smem 92.7KB/CTA -> 2 CTAs/SM; softmax of one CTA overlaps mma of the other.
// ===========================================================================
#define SQB 144                       // 64 bf16 + 8 pad, 16B-aligned rows
#define QPL (64*SQB)                  // 9216 B per Q plane
#define OFF_QL QPL
#define OFF_STAGE (2*QPL)             // 18432
#define SKL QPL                       // K lo offset within stage
#define SVH (2*QPL)                   // V hi
#define SVL (3*QPL)                   // V lo
#define STAGE_SZ (4*QPL)              // 36864
#define OFF_MS (OFF_STAGE + 2*STAGE_SZ)   // 92160
#define ATT_SMEM (OFF_MS + 512)           // 92672

__global__ __launch_bounds__(128, 2)
void attn_tc()
{
    extern __shared__ char sm[];
    const u32 sb = smem_u32(sm);
    const int tid = threadIdx.x;
    const int wid = tid >> 5, lid = tid & 31;
    const int qr = lid >> 2, qc = lid & 3;
    const int qt = blockIdx.x, h = blockIdx.y, b = blockIdx.z;
    const int bh = b*Hn + h;

    const float* Qg = g_Q + ((size_t)bh*Sn + qt*64)*Dn;
    const float* mk = g_maskf + b*Sn;
    const unsigned short* Khg = g_Kbh + (size_t)bh*Sn*Dn;
    const unsigned short* Klg = g_Kbl + (size_t)bh*Sn*Dn;
    const unsigned short* Vhg = g_Vth + (size_t)bh*Dn*Sn;
    const unsigned short* Vlg = g_Vtl + (size_t)bh*Dn*Sn;
    float* mS = (float*)(sm + OFF_MS);

    // ---- Q load (64 rows x 64 d) + 0.125 scale + split into smem ----
    #pragma unroll
    for (int i = 0; i < 8; i++) {
        int f4 = tid + (i << 7);
        int row = f4 >> 4, dim = (f4 & 15) << 2;
        float4 v = *(const float4*)&Qg[row*Dn + dim];
        v.x *= 0.125f; v.y *= 0.125f; v.z *= 0.125f; v.w *= 0.125f;
        u32 h0,l0,h1,l1,h2,l2,h3,l3;
        bsplit(v.x,h0,l0); bsplit(v.y,h1,l1); bsplit(v.z,h2,l2); bsplit(v.w,h3,l3);
        *(uint2*)(sm + row*SQB + dim*2)          = make_uint2(h0|(h1<<16), h2|(h3<<16));
        *(uint2*)(sm + OFF_QL + row*SQB + dim*2) = make_uint2(l0|(l1<<16), l2|(l3<<16));
    }

    // ---- async loader: key-tile 64 => 2048 x 16B chunks over 128 threads ----
    auto issue = [&](int kt, int st) {
        const u32 stg = sb + OFF_STAGE + st*STAGE_SZ;
        #pragma unroll
        for (int i = 0; i < 16; i++) {
            int c = tid + (i << 7);
            if (c < 1024) {
                int pl = c >> 9, idx = c & 511;
                int row = idx >> 3, col = idx & 7;
                const unsigned short* src = (pl ? Klg : Khg)
                    + (size_t)(kt*64 + row)*Dn + col*8;
                CP_ASYNC16(stg + pl*SKL + row*SQB + col*16, src);
            } else {
                int c2 = c - 1024;
                int pl = c2 >> 9, idx = c2 & 511;
                int d = idx >> 3, col = idx & 7;
                const unsigned short* src = (pl ? Vlg : Vhg)
                    + (size_t)d*Sn + kt*64 + col*8;
                CP_ASYNC16(stg + SVH + pl*(SVL-SVH) + d*SQB + col*16, src);
            }
        }
        if (tid < 64) mS[st*64 + tid] = mk[kt*64 + tid];
        CP_COMMIT();
    };

    float m0 = -INFINITY, m1 = -INFINITY, l0 = 0.f, l1 = 0.f;
    float acc[8][4];
    #pragma unroll
    for (int nt = 0; nt < 8; nt++)
        #pragma unroll
        for (int r = 0; r < 4; r++) acc[nt][r] = 0.f;

    issue(0, 0);

    const u32 nOff8  = ((lid >> 4) & 1) * 8 + (lid & 7);
    const u32 kOff16 = ((lid >> 3) & 1) * 16;
    const u32 qAhi = sb + (u32)(wid*16 + (lid & 15))*SQB + ((lid >> 4) << 4);

    for (int kt = 0; kt < Sn/64; kt++) {
        const int st = kt & 1;
        CP_WAIT0();
        __syncthreads();
        if (kt + 1 < Sn/64) issue(kt + 1, 1 - st);

        const u32 KHu = sb + OFF_STAGE + st*STAGE_SZ;
        const u32 KLu = KHu + SKL;
        const u32 VHu = KHu + SVH;
        const u32 VLu = KHu + SVL;

        // ---- QK^T: scores [16 x 64] per warp ----
        float sc[8][4];
        #pragma unroll
        for (int nt = 0; nt < 8; nt++)
            #pragma unroll
            for (int r = 0; r < 4; r++) sc[nt][r] = 0.f;

        #pragma unroll
        for (int ks = 0; ks < 4; ks++) {
            u32 ah[4], al[4];
            LDSM_X4(ah[0], ah[1], ah[2], ah[3], qAhi + ks*32);
            LDSM_X4(al[0], al[1], al[2], al[3], qAhi + OFF_QL + ks*32);
            #pragma unroll
            for (int p = 0; p < 4; p++) {
                u32 badr = (u32)(p*16 + nOff8)*SQB + kOff16 + ks*32;
                u32 bh0, bh1, bh2, bh3, bl0, bl1, bl2, bl3;
                LDSM_X4(bh0, bh1, bh2, bh3, KHu + badr);
                LDSM_X4(bl0, bl1, bl2, bl3, KLu + badr);
                mma_bf16(sc[2*p],   ah[0], ah[1], ah[2], ah[3], bh0, bh1);
                mma_bf16(sc[2*p],   ah[0], ah[1], ah[2], ah[3], bl0, bl1);
                mma_bf16(sc[2*p],   al[0], al[1], al[2], al[3], bh0, bh1);
                mma_bf16(sc[2*p+1], ah[0], ah[1], ah[2], ah[3], bh2, bh3);
                mma_bf16(sc[2*p+1], ah[0], ah[1], ah[2], ah[3], bl2, bl3);
                mma_bf16(sc[2*p+1], al[0], al[1], al[2], al[3], bh2, bh3);
            }
        }

        // ---- mask ----
        const float* msk = mS + st*64;
        #pragma unroll
        for (int nt = 0; nt < 8; nt++) {
            int c0 = nt*8 + qc*2;
            if (msk[c0]   != 0.f) { sc[nt][0] = -1e9f; sc[nt][2] = -1e9f; }
            if (msk[c0+1] != 0.f) { sc[nt][1] = -1e9f; sc[nt][3] = -1e9f; }
        }

        // ---- online softmax ----
        float mx0 = -INFINITY, mx1 = -INFINITY;
        #pragma unroll
        for (int nt = 0; nt < 8; nt++) {
            mx0 = fmaxf(mx0, fmaxf(sc[nt][0], sc[nt][1]));
            mx1 = fmaxf(mx1, fmaxf(sc[nt][2], sc[nt][3]));
        }
        mx0 = fmaxf(mx0, __shfl_xor_sync(0xffffffffu, mx0, 1));
        mx0 = fmaxf(mx0, __shfl_xor_sync(0xffffffffu, mx0, 2));
        mx1 = fmaxf(mx1, __shfl_xor_sync(0xffffffffu, mx1, 1));
        mx1 = fmaxf(mx1, __shfl_xor_sync(0xffffffffu, mx1, 2));
        float mn0 = fmaxf(m0, mx0), mn1 = fmaxf(m1, mx1);
        float fs0 = __expf(m0 - mn0), fs1 = __expf(m1 - mn1);
        m0 = mn0; m1 = mn1;

        float ps0 = 0.f, ps1 = 0.f;
        #pragma unroll
        for (int nt = 0; nt < 8; nt++) {
            float p0 = __expf(sc[nt][0] - mn0);
            float p1 = __expf(sc[nt][1] - mn0);
            float p2 = __expf(sc[nt][2] - mn1);
            float p3 = __expf(sc[nt][3] - mn1);
            ps0 += p0 + p1; ps1 += p2 + p3;
            sc[nt][0] = p0; sc[nt][1] = p1; sc[nt][2] = p2; sc[nt][3] = p3;
        }
        ps0 += __shfl_xor_sync(0xffffffffu, ps0, 1);
        ps0 += __shfl_xor_sync(0xffffffffu, ps0, 2);
        ps1 += __shfl_xor_sync(0xffffffffu, ps1, 1);
        ps1 += __shfl_xor_sync(0xffffffffu, ps1, 2);
        l0 = l0*fs0 + ps0;
        l1 = l1*fs1 + ps1;

        #pragma unroll
        for (int nt = 0; nt < 8; nt++) {
            acc[nt][0] *= fs0; acc[nt][1] *= fs0;
            acc[nt][2] *= fs1; acc[nt][3] *= fs1;
        }

        // ---- PV: P [16x64] x V [64x64] ----
        u32 pah[4][4], pal[4][4];
        #pragma unroll
        for (int ksl = 0; ksl < 4; ksl++) {
            psplit2(sc[2*ksl][0],   sc[2*ksl][1],   pah[ksl][0], pal[ksl][0]);
            psplit2(sc[2*ksl][2],   sc[2*ksl][3],   pah[ksl][1], pal[ksl][1]);
            psplit2(sc[2*ksl+1][0], sc[2*ksl+1][1], pah[ksl][2], pal[ksl][2]);
            psplit2(sc[2*ksl+1][2], sc[2*ksl+1][3], pah[ksl][3], pal[ksl][3]);
        }
        #pragma unroll
        for (int ksl = 0; ksl < 4; ksl++) {
            #pragma unroll
            for (int p = 0; p < 4; p++) {
                u32 vadr = (u32)(p*16 + nOff8)*SQB + kOff16 + ksl*32;
                u32 vh0, vh1, vh2, vh3, vl0, vl1, vl2, vl3;
                LDSM_X4(vh0, vh1, vh2, vh3, VHu + vadr);
                LDSM_X4(vl0, vl1, vl2, vl3, VLu + vadr);
                mma_bf16(acc[2*p], pah[ksl][0], pah[ksl][1], pah[ksl][2],
                         pah[ksl][3], vh0, vh1);
                mma_bf16(acc[2*p], pal[ksl][0], pal[ksl][1], pal[ksl][2],
                         pal[ksl][3], vh0, vh1);
                mma_bf16(acc[2*p], pah[ksl][0], pah[ksl][1], pah[ksl][2],
                         pah[ksl][3], vl0, vl1);
                mma_bf16(acc[2*p+1], pah[ksl][0], pah[ksl][1], pah[ksl][2],
                         pah[ksl][3], vh2, vh3);
                mma_bf16(acc[2*p+1], pal[ksl][0], pal[ksl][1], pal[ksl][2],
                         pal[ksl][3], vh2, vh3);
                mma_bf16(acc[2*p+1], pah[ksl][0], pah[ksl][1], pah[ksl][2],
                         pah[ksl][3], vl2, vl3);
            }
        }
    }

    // ---- epilogue ----
    float inv0 = 1.f / l0, inv1 = 1.f / l1;
    int row0 = qt*64 + wid*16 + qr;
    #pragma unroll
    for (int nt = 0; nt < 8; nt++) {
        int d = h*64 + nt*8 + qc*2;
        *(float2*)&g_A[((size_t)(b*Sn + row0))*En + d] =
            make_float2(acc[nt][0]*inv0, acc[nt][1]*inv0);
        *(float2*)&g_A[((size_t)(b*Sn + row0 + 8))*En + d] =
            make_float2(acc[nt][2]*inv1, acc[nt][3]*inv1);
    }
}

// ---------------------------------------------------------------------------
extern "C" void kernel_launch(void* const* d_in, const int* in_sizes, int n_in,
                              void* d_out, int out_size)
{
    const float* x  = (const float*)d_in[0];
    const unsigned char* mask = (const unsigned char*)d_in[1];
    const float* Wq = (const float*)d_in[2];
    const float* bq = (const float*)d_in[3];
    const float* Wk = (const float*)d_in[4];
    const float* bk = (const float*)d_in[5];
    const float* Wv = (const float*)d_in[6];
    const float* bv = (const float*)d_in[7];
    const float* Wo = (const float*)d_in[8];
    const float* bo = (const float*)d_in[9];
    float* out = (float*)d_out;

    cudaFuncSetAttribute(gemm_mma<1>,
                         cudaFuncAttributeMaxDynamicSharedMemorySize, GEMM_SMEM);
    cudaFuncSetAttribute(gemm_mma<0>,
                         cudaFuncAttributeMaxDynamicSharedMemorySize, GEMM_SMEM);
    cudaFuncSetAttribute(attn_tc,
                         cudaFuncAttributeMaxDynamicSharedMemorySize, ATT_SMEM);

    mask_prep<<<1, 256>>>(mask);

    gemm_mma<1><<<dim3(En/128, Mn/128, 3), 256, GEMM_SMEM>>>(
        x, Wq, bq, Wk, bk, Wv, bv, nullptr);

    kv_prep<<<dim3(Sn/32, Hn, Bn), 256>>>();

    attn_tc<<<dim3(Sn/64, Hn, Bn), 128, ATT_SMEM>>>();

    gemm_mma<0><<<dim3(En/128, Mn/128, 1), 256, GEMM_SMEM>>>(
        nullptr, Wo, bo, nullptr, nullptr, nullptr, nullptr, out);
}